// round 1
// baseline (speedup 1.0000x reference)
#include <cuda_runtime.h>
#include <math.h>

// ---------------- problem constants ----------------
#define BSZ   64
#define LSEQ  2688
#define CDIM  256
#define WWIN  42
#define SSH   21
#define NHEAD 8
#define HDIM  32
#define NWIN  64            // windows per batch element
#define MLPH  1024
#define NTOK  (BSZ*LSEQ)    // 172032
#define NBWIN (BSZ*NWIN)    // 4096

// ---------------- scratch (device globals; no allocation allowed) ----------
__device__ float g_h0 [(size_t)NTOK*CDIM];      // LN1 + rolled
__device__ float g_qkv[(size_t)NTOK*3*CDIM];    // qkv
__device__ float g_att[(size_t)NTOK*CDIM];      // attention output
__device__ float g_prj[(size_t)NTOK*CDIM];      // proj output (window layout)
__device__ float g_x1 [(size_t)NTOK*CDIM];      // residual 1
__device__ float g_m  [(size_t)NTOK*CDIM];      // LN2 output
__device__ float g_f1 [(size_t)NTOK*MLPH];      // fc1+gelu output

// ---------------- LayerNorm (+cyclic shift) : one warp per token ----------
__global__ __launch_bounds__(256) void ln_roll_kernel(
    const float* __restrict__ x, const float* __restrict__ g,
    const float* __restrict__ b, float* __restrict__ out)
{
    int token = blockIdx.x * 8 + (threadIdx.x >> 5);
    int lane  = threadIdx.x & 31;
    int bi = token / LSEQ, l = token % LSEQ;
    int src = bi * LSEQ + (l + SSH) % LSEQ;      // roll(-S): out[l] = in[l+S]
    const float4* xr = (const float4*)(x + (size_t)src * CDIM);
    float4 v0 = xr[lane], v1 = xr[lane + 32];
    float s  = v0.x+v0.y+v0.z+v0.w + v1.x+v1.y+v1.z+v1.w;
    float ss = v0.x*v0.x+v0.y*v0.y+v0.z*v0.z+v0.w*v0.w
             + v1.x*v1.x+v1.y*v1.y+v1.z*v1.z+v1.w*v1.w;
    #pragma unroll
    for (int o = 16; o; o >>= 1) {
        s  += __shfl_xor_sync(0xffffffffu, s,  o);
        ss += __shfl_xor_sync(0xffffffffu, ss, o);
    }
    float mean = s * (1.0f/CDIM);
    float var  = ss * (1.0f/CDIM) - mean*mean;
    float inv  = rsqrtf(var + 1e-5f);
    float4 g0 = ((const float4*)g)[lane], g1 = ((const float4*)g)[lane+32];
    float4 b0 = ((const float4*)b)[lane], b1 = ((const float4*)b)[lane+32];
    float4 o0, o1;
    o0.x=(v0.x-mean)*inv*g0.x+b0.x; o0.y=(v0.y-mean)*inv*g0.y+b0.y;
    o0.z=(v0.z-mean)*inv*g0.z+b0.z; o0.w=(v0.w-mean)*inv*g0.w+b0.w;
    o1.x=(v1.x-mean)*inv*g1.x+b1.x; o1.y=(v1.y-mean)*inv*g1.y+b1.y;
    o1.z=(v1.z-mean)*inv*g1.z+b1.z; o1.w=(v1.w-mean)*inv*g1.w+b1.w;
    float4* orow = (float4*)(out + (size_t)token * CDIM);
    orow[lane] = o0; orow[lane+32] = o1;
}

// ------------- residual (reverse shift) + LayerNorm2 : warp per token -----
__global__ __launch_bounds__(256) void resid_ln2_kernel(
    const float* __restrict__ x,  const float* __restrict__ po,
    const float* __restrict__ g,  const float* __restrict__ b,
    float* __restrict__ x1, float* __restrict__ m)
{
    int token = blockIdx.x * 8 + (threadIdx.x >> 5);
    int lane  = threadIdx.x & 31;
    int bi = token / LSEQ, l = token % LSEQ;
    int src = bi * LSEQ + (l - SSH + LSEQ) % LSEQ;   // roll(+S)
    const float4* xr = (const float4*)(x  + (size_t)token * CDIM);
    const float4* pr = (const float4*)(po + (size_t)src   * CDIM);
    float4 a0 = xr[lane], a1 = xr[lane+32];
    float4 p0 = pr[lane], p1 = pr[lane+32];
    float4 v0, v1;
    v0.x=a0.x+p0.x; v0.y=a0.y+p0.y; v0.z=a0.z+p0.z; v0.w=a0.w+p0.w;
    v1.x=a1.x+p1.x; v1.y=a1.y+p1.y; v1.z=a1.z+p1.z; v1.w=a1.w+p1.w;
    float4* x1r = (float4*)(x1 + (size_t)token * CDIM);
    x1r[lane] = v0; x1r[lane+32] = v1;
    float s  = v0.x+v0.y+v0.z+v0.w + v1.x+v1.y+v1.z+v1.w;
    float ss = v0.x*v0.x+v0.y*v0.y+v0.z*v0.z+v0.w*v0.w
             + v1.x*v1.x+v1.y*v1.y+v1.z*v1.z+v1.w*v1.w;
    #pragma unroll
    for (int o = 16; o; o >>= 1) {
        s  += __shfl_xor_sync(0xffffffffu, s,  o);
        ss += __shfl_xor_sync(0xffffffffu, ss, o);
    }
    float mean = s * (1.0f/CDIM);
    float var  = ss * (1.0f/CDIM) - mean*mean;
    float inv  = rsqrtf(var + 1e-5f);
    float4 g0 = ((const float4*)g)[lane], g1 = ((const float4*)g)[lane+32];
    float4 b0 = ((const float4*)b)[lane], b1 = ((const float4*)b)[lane+32];
    float4 o0, o1;
    o0.x=(v0.x-mean)*inv*g0.x+b0.x; o0.y=(v0.y-mean)*inv*g0.y+b0.y;
    o0.z=(v0.z-mean)*inv*g0.z+b0.z; o0.w=(v0.w-mean)*inv*g0.w+b0.w;
    o1.x=(v1.x-mean)*inv*g1.x+b1.x; o1.y=(v1.y-mean)*inv*g1.y+b1.y;
    o1.z=(v1.z-mean)*inv*g1.z+b1.z; o1.w=(v1.w-mean)*inv*g1.w+b1.w;
    float4* mr = (float4*)(m + (size_t)token * CDIM);
    mr[lane] = o0; mr[lane+32] = o1;
}

// ---------------- fp32 SGEMM 128x128x8, 8x8/thread --------------------------
// EPI: 0 = +bias ; 1 = +bias then GELU(exact) ; 2 = +bias +res
__device__ __forceinline__ float gelu_exact(float v) {
    return 0.5f * v * (1.0f + erff(v * 0.70710678118654752f));
}

template<int EPI>
__global__ __launch_bounds__(256) void sgemm_kernel(
    const float* __restrict__ A, const float* __restrict__ Bw,
    const float* __restrict__ bias, const float* __restrict__ res,
    float* __restrict__ C, int M, int N, int K)
{
    __shared__ float As[8][128];
    __shared__ float Bs[8][128];
    const int tid = threadIdx.x;
    const int bx = blockIdx.x, by = blockIdx.y;
    const int tx = tid & 15, ty = tid >> 4;

    float acc[8][8];
    #pragma unroll
    for (int i = 0; i < 8; i++)
        #pragma unroll
        for (int j = 0; j < 8; j++) acc[i][j] = 0.0f;

    const int aRow = tid >> 1,  aCol = (tid & 1) << 2;
    const int bRow = tid >> 5,  bCol = (tid & 31) << 2;
    const float* Ap = A  + (size_t)(by*128 + aRow) * K + aCol;
    const float* Bp = Bw + (size_t)bRow * N + bx*128 + bCol;

    for (int k0 = 0; k0 < K; k0 += 8) {
        float4 a  = *(const float4*)Ap;
        float4 bb = *(const float4*)Bp;
        As[aCol+0][aRow] = a.x;
        As[aCol+1][aRow] = a.y;
        As[aCol+2][aRow] = a.z;
        As[aCol+3][aRow] = a.w;
        *(float4*)&Bs[bRow][bCol] = bb;
        __syncthreads();
        #pragma unroll
        for (int kk = 0; kk < 8; kk++) {
            float4 a0 = *(const float4*)&As[kk][ty*8];
            float4 a1 = *(const float4*)&As[kk][ty*8+4];
            float4 c0 = *(const float4*)&Bs[kk][tx*8];
            float4 c1 = *(const float4*)&Bs[kk][tx*8+4];
            float ar[8] = {a0.x,a0.y,a0.z,a0.w,a1.x,a1.y,a1.z,a1.w};
            float br[8] = {c0.x,c0.y,c0.z,c0.w,c1.x,c1.y,c1.z,c1.w};
            #pragma unroll
            for (int i = 0; i < 8; i++)
                #pragma unroll
                for (int j = 0; j < 8; j++) acc[i][j] += ar[i]*br[j];
        }
        __syncthreads();
        Ap += 8;
        Bp += (size_t)8 * N;
    }

    const int row0 = by*128 + ty*8;
    const int col0 = bx*128 + tx*8;
    float bv[8];
    #pragma unroll
    for (int j = 0; j < 8; j++) bv[j] = bias[col0 + j];

    #pragma unroll
    for (int i = 0; i < 8; i++) {
        size_t off = (size_t)(row0 + i) * N + col0;
        float v[8];
        #pragma unroll
        for (int j = 0; j < 8; j++) {
            v[j] = acc[i][j] + bv[j];
            if (EPI == 1) v[j] = gelu_exact(v[j]);
            if (EPI == 2) v[j] += res[off + j];
        }
        float4 o0 = {v[0], v[1], v[2], v[3]};
        float4 o1 = {v[4], v[5], v[6], v[7]};
        *(float4*)&C[off]     = o0;
        *(float4*)&C[off + 4] = o1;
    }
}

// ---------------- windowed attention: one block per (window, head) ---------
__global__ __launch_bounds__(256) void attn_kernel(
    const float* __restrict__ qkv, const float* __restrict__ bias_table,
    float* __restrict__ out)
{
    const int w = blockIdx.x;    // 0..4095
    const int h = blockIdx.y;    // 0..7
    // padded stride 33 to avoid bank conflicts on K^T / Q reads
    __shared__ float sq[WWIN*33];
    __shared__ float sk[WWIN*33];
    __shared__ float sv[WWIN*33];
    __shared__ float ss[WWIN*WWIN];

    const int tid = threadIdx.x;
    for (int i = tid; i < WWIN*HDIM; i += 256) {
        int n = i >> 5, d = i & 31;
        size_t base = ((size_t)w*WWIN + n)*768 + h*HDIM + d;
        sq[n*33 + d] = qkv[base];
        sk[n*33 + d] = qkv[base + 256];
        sv[n*33 + d] = qkv[base + 512];
    }
    __syncthreads();

    const bool lastw = ((w & (NWIN-1)) == NWIN-1);
    for (int idx = tid; idx < WWIN*WWIN; idx += 256) {
        int n = idx / WWIN, mm = idx - n*WWIN;
        const float* qn = &sq[n*33];
        const float* km = &sk[mm*33];
        float acc = 0.0f;
        #pragma unroll
        for (int d = 0; d < HDIM; d++) acc += qn[d]*km[d];
        acc *= 0.17677669529663688f;                       // 1/sqrt(32)
        acc += __ldg(&bias_table[(mm - n + WWIN - 1)*NHEAD + h]);
        if (lastw && ((n < SSH) != (mm < SSH))) acc -= 100.0f;
        ss[idx] = acc;
    }
    __syncthreads();

    const int warp = tid >> 5, lane = tid & 31;
    for (int n = warp; n < WWIN; n += 8) {
        float v0 = ss[n*WWIN + lane];
        float v1 = (lane < WWIN-32) ? ss[n*WWIN + 32 + lane] : -1e30f;
        float mx = fmaxf(v0, v1);
        #pragma unroll
        for (int o = 16; o; o >>= 1) mx = fmaxf(mx, __shfl_xor_sync(0xffffffffu, mx, o));
        float e0 = __expf(v0 - mx);
        float e1 = (lane < WWIN-32) ? __expf(v1 - mx) : 0.0f;
        float sm = e0 + e1;
        #pragma unroll
        for (int o = 16; o; o >>= 1) sm += __shfl_xor_sync(0xffffffffu, sm, o);
        float r = 1.0f / sm;
        ss[n*WWIN + lane] = e0 * r;
        if (lane < WWIN-32) ss[n*WWIN + 32 + lane] = e1 * r;
    }
    __syncthreads();

    for (int i = tid; i < WWIN*HDIM; i += 256) {
        int n = i >> 5, d = i & 31;
        const float* pn = &ss[n*WWIN];
        float acc = 0.0f;
        #pragma unroll
        for (int mm = 0; mm < WWIN; mm++) acc += pn[mm]*sv[mm*33 + d];
        out[((size_t)w*WWIN + n)*CDIM + h*HDIM + d] = acc;
    }
}

// ---------------- host-side launch -----------------------------------------
extern "C" void kernel_launch(void* const* d_in, const int* in_sizes, int n_in,
                              void* d_out, int out_size)
{
    const float* x     = (const float*)d_in[0];
    const float* n1g   = (const float*)d_in[1];
    const float* n1b   = (const float*)d_in[2];
    const float* qkv_w = (const float*)d_in[3];
    const float* qkv_b = (const float*)d_in[4];
    const float* bt    = (const float*)d_in[5];
    const float* pw    = (const float*)d_in[6];
    const float* pb    = (const float*)d_in[7];
    const float* n2g   = (const float*)d_in[8];
    const float* n2b   = (const float*)d_in[9];
    const float* f1w   = (const float*)d_in[10];
    const float* f1b   = (const float*)d_in[11];
    const float* f2w   = (const float*)d_in[12];
    const float* f2b   = (const float*)d_in[13];
    float* out = (float*)d_out;

    float *h0, *qkvp, *att, *prj, *x1, *m, *f1;
    cudaGetSymbolAddress((void**)&h0,   g_h0);
    cudaGetSymbolAddress((void**)&qkvp, g_qkv);
    cudaGetSymbolAddress((void**)&att,  g_att);
    cudaGetSymbolAddress((void**)&prj,  g_prj);
    cudaGetSymbolAddress((void**)&x1,   g_x1);
    cudaGetSymbolAddress((void**)&m,    g_m);
    cudaGetSymbolAddress((void**)&f1,   g_f1);

    const int MBLK = NTOK / 128;   // 1344

    // 1) LN1 + roll(-S)
    ln_roll_kernel<<<NTOK/8, 256>>>(x, n1g, n1b, h0);
    // 2) QKV GEMM  [NTOK,256] @ [256,768]
    sgemm_kernel<0><<<dim3(768/128, MBLK), 256>>>(h0, qkv_w, qkv_b, nullptr, qkvp, NTOK, 768, 256);
    // 3) windowed attention
    attn_kernel<<<dim3(NBWIN, NHEAD), 256>>>(qkvp, bt, att);
    // 4) proj GEMM  [NTOK,256] @ [256,256]
    sgemm_kernel<0><<<dim3(256/128, MBLK), 256>>>(att, pw, pb, nullptr, prj, NTOK, 256, 256);
    // 5) residual (roll +S) + LN2
    resid_ln2_kernel<<<NTOK/8, 256>>>(x, prj, n2g, n2b, x1, m);
    // 6) FC1 + GELU  [NTOK,256] @ [256,1024]
    sgemm_kernel<1><<<dim3(1024/128, MBLK), 256>>>(m, f1w, f1b, nullptr, f1, NTOK, 1024, 256);
    // 7) FC2 + residual  [NTOK,1024] @ [1024,256]
    sgemm_kernel<2><<<dim3(256/128, MBLK), 256>>>(f1, f2w, f2b, x1, out, NTOK, 256, 1024);
}

// round 2
// speedup vs baseline: 2.0010x; 2.0010x over previous
#include <cuda_runtime.h>
#include <math.h>
#include <stdint.h>

// ---------------- problem constants ----------------
#define BSZ   64
#define LSEQ  2688
#define CDIM  256
#define WWIN  42
#define SSH   21
#define NHEAD 8
#define HDIM  32
#define NWIN  64
#define MLPH  1024
#define NTOK  (BSZ*LSEQ)    // 172032
#define NBWIN (BSZ*NWIN)    // 4096

// ---------------- scratch ----------------
__device__ float g_h0 [(size_t)NTOK*CDIM];
__device__ float g_qkv[(size_t)NTOK*3*CDIM];
__device__ float g_att[(size_t)NTOK*CDIM];
__device__ float g_prj[(size_t)NTOK*CDIM];
__device__ float g_x1 [(size_t)NTOK*CDIM];
__device__ float g_m  [(size_t)NTOK*CDIM];
__device__ float g_f1 [(size_t)NTOK*MLPH];

// ---------------- LayerNorm (+cyclic shift) ----------
__global__ __launch_bounds__(256) void ln_roll_kernel(
    const float* __restrict__ x, const float* __restrict__ g,
    const float* __restrict__ b, float* __restrict__ out)
{
    int token = blockIdx.x * 8 + (threadIdx.x >> 5);
    int lane  = threadIdx.x & 31;
    int bi = token / LSEQ, l = token % LSEQ;
    int src = bi * LSEQ + (l + SSH) % LSEQ;
    const float4* xr = (const float4*)(x + (size_t)src * CDIM);
    float4 v0 = xr[lane], v1 = xr[lane + 32];
    float s  = v0.x+v0.y+v0.z+v0.w + v1.x+v1.y+v1.z+v1.w;
    float ss = v0.x*v0.x+v0.y*v0.y+v0.z*v0.z+v0.w*v0.w
             + v1.x*v1.x+v1.y*v1.y+v1.z*v1.z+v1.w*v1.w;
    #pragma unroll
    for (int o = 16; o; o >>= 1) {
        s  += __shfl_xor_sync(0xffffffffu, s,  o);
        ss += __shfl_xor_sync(0xffffffffu, ss, o);
    }
    float mean = s * (1.0f/CDIM);
    float var  = ss * (1.0f/CDIM) - mean*mean;
    float inv  = rsqrtf(var + 1e-5f);
    float4 g0 = ((const float4*)g)[lane], g1 = ((const float4*)g)[lane+32];
    float4 b0 = ((const float4*)b)[lane], b1 = ((const float4*)b)[lane+32];
    float4 o0, o1;
    o0.x=(v0.x-mean)*inv*g0.x+b0.x; o0.y=(v0.y-mean)*inv*g0.y+b0.y;
    o0.z=(v0.z-mean)*inv*g0.z+b0.z; o0.w=(v0.w-mean)*inv*g0.w+b0.w;
    o1.x=(v1.x-mean)*inv*g1.x+b1.x; o1.y=(v1.y-mean)*inv*g1.y+b1.y;
    o1.z=(v1.z-mean)*inv*g1.z+b1.z; o1.w=(v1.w-mean)*inv*g1.w+b1.w;
    float4* orow = (float4*)(out + (size_t)token * CDIM);
    orow[lane] = o0; orow[lane+32] = o1;
}

// ------------- residual (reverse shift) + LayerNorm2 -----
__global__ __launch_bounds__(256) void resid_ln2_kernel(
    const float* __restrict__ x,  const float* __restrict__ po,
    const float* __restrict__ g,  const float* __restrict__ b,
    float* __restrict__ x1, float* __restrict__ m)
{
    int token = blockIdx.x * 8 + (threadIdx.x >> 5);
    int lane  = threadIdx.x & 31;
    int bi = token / LSEQ, l = token % LSEQ;
    int src = bi * LSEQ + (l - SSH + LSEQ) % LSEQ;
    const float4* xr = (const float4*)(x  + (size_t)token * CDIM);
    const float4* pr = (const float4*)(po + (size_t)src   * CDIM);
    float4 a0 = xr[lane], a1 = xr[lane+32];
    float4 p0 = pr[lane], p1 = pr[lane+32];
    float4 v0, v1;
    v0.x=a0.x+p0.x; v0.y=a0.y+p0.y; v0.z=a0.z+p0.z; v0.w=a0.w+p0.w;
    v1.x=a1.x+p1.x; v1.y=a1.y+p1.y; v1.z=a1.z+p1.z; v1.w=a1.w+p1.w;
    float4* x1r = (float4*)(x1 + (size_t)token * CDIM);
    x1r[lane] = v0; x1r[lane+32] = v1;
    float s  = v0.x+v0.y+v0.z+v0.w + v1.x+v1.y+v1.z+v1.w;
    float ss = v0.x*v0.x+v0.y*v0.y+v0.z*v0.z+v0.w*v0.w
             + v1.x*v1.x+v1.y*v1.y+v1.z*v1.z+v1.w*v1.w;
    #pragma unroll
    for (int o = 16; o; o >>= 1) {
        s  += __shfl_xor_sync(0xffffffffu, s,  o);
        ss += __shfl_xor_sync(0xffffffffu, ss, o);
    }
    float mean = s * (1.0f/CDIM);
    float var  = ss * (1.0f/CDIM) - mean*mean;
    float inv  = rsqrtf(var + 1e-5f);
    float4 g0 = ((const float4*)g)[lane], g1 = ((const float4*)g)[lane+32];
    float4 b0 = ((const float4*)b)[lane], b1 = ((const float4*)b)[lane+32];
    float4 o0, o1;
    o0.x=(v0.x-mean)*inv*g0.x+b0.x; o0.y=(v0.y-mean)*inv*g0.y+b0.y;
    o0.z=(v0.z-mean)*inv*g0.z+b0.z; o0.w=(v0.w-mean)*inv*g0.w+b0.w;
    o1.x=(v1.x-mean)*inv*g1.x+b1.x; o1.y=(v1.y-mean)*inv*g1.y+b1.y;
    o1.z=(v1.z-mean)*inv*g1.z+b1.z; o1.w=(v1.w-mean)*inv*g1.w+b1.w;
    float4* mr = (float4*)(m + (size_t)token * CDIM);
    mr[lane] = o0; mr[lane+32] = o1;
}

// ---------------- tf32 tensor-core GEMM --------------------
// 128x128 block tile, BK=16, 8 warps (2m x 4n), warp tile 64x32,
// mma.sync.m16n8k8.tf32, fp32 accumulate.
// EPI: 0 = +bias ; 1 = +bias,GELU ; 2 = +bias,+res

__device__ __forceinline__ float gelu_exact(float v) {
    return 0.5f * v * (1.0f + erff(v * 0.70710678118654752f));
}
__device__ __forceinline__ float f2tf32(float f) {
    uint32_t u; asm("cvt.rna.tf32.f32 %0, %1;" : "=r"(u) : "f"(f));
    return __uint_as_float(u);
}
__device__ __forceinline__ void mma_tf32(
    float& c0, float& c1, float& c2, float& c3,
    uint32_t a0, uint32_t a1, uint32_t a2, uint32_t a3,
    uint32_t b0, uint32_t b1)
{
    asm volatile(
        "mma.sync.aligned.m16n8k8.row.col.f32.tf32.tf32.f32 "
        "{%0,%1,%2,%3}, {%4,%5,%6,%7}, {%8,%9}, {%0,%1,%2,%3};\n"
        : "+f"(c0), "+f"(c1), "+f"(c2), "+f"(c3)
        : "r"(a0), "r"(a1), "r"(a2), "r"(a3), "r"(b0), "r"(b1));
}

#define BK   16
#define LDSA 136   // 128 + 8 pad: conflict-free fragment LDS
#define LDSB 136

template<int EPI>
__global__ __launch_bounds__(256) void tgemm_kernel(
    const float* __restrict__ A, const float* __restrict__ Bw,
    const float* __restrict__ bias, const float* __restrict__ res,
    float* __restrict__ C, int M, int N, int K)
{
    __shared__ float As[2][BK][LDSA];
    __shared__ float Bs[2][BK][LDSB];

    const int tid  = threadIdx.x;
    const int warp = tid >> 5, lane = tid & 31;
    const int wm  = (warp >> 2) * 64;   // 0 / 64
    const int wn  = (warp & 3) * 32;    // 0,32,64,96
    const int grp = lane & 3;
    const int qid = lane >> 2;

    const int aRow = tid >> 1;
    const int aCol = (tid & 1) << 2;
    const int bRow = tid >> 5;
    const int bCol = (tid & 31) << 2;

    const float* Ap = A  + (size_t)(blockIdx.y*128 + aRow) * K + aCol;
    const float* Bp = Bw + (size_t)bRow * N + blockIdx.x*128 + bCol;

    float acc[4][4][4];
    #pragma unroll
    for (int i = 0; i < 4; i++)
        #pragma unroll
        for (int j = 0; j < 4; j++)
            #pragma unroll
            for (int t = 0; t < 4; t++) acc[i][j][t] = 0.0f;

    // prologue: tile 0 -> smem buf 0
    {
        float4 a0 = *(const float4*)Ap;
        float4 a1 = *(const float4*)(Ap + 8);
        float4 b0 = *(const float4*)Bp;
        float4 b1 = *(const float4*)(Bp + (size_t)8*N);
        As[0][aCol+0][aRow] = f2tf32(a0.x); As[0][aCol+1][aRow] = f2tf32(a0.y);
        As[0][aCol+2][aRow] = f2tf32(a0.z); As[0][aCol+3][aRow] = f2tf32(a0.w);
        As[0][aCol+8][aRow] = f2tf32(a1.x); As[0][aCol+9][aRow] = f2tf32(a1.y);
        As[0][aCol+10][aRow]= f2tf32(a1.z); As[0][aCol+11][aRow]= f2tf32(a1.w);
        float4 c0 = {f2tf32(b0.x), f2tf32(b0.y), f2tf32(b0.z), f2tf32(b0.w)};
        float4 c1 = {f2tf32(b1.x), f2tf32(b1.y), f2tf32(b1.z), f2tf32(b1.w)};
        *(float4*)&Bs[0][bRow  ][bCol] = c0;
        *(float4*)&Bs[0][bRow+8][bCol] = c1;
    }
    __syncthreads();

    int buf = 0;
    for (int k0 = 0; ; k0 += BK) {
        const bool last = (k0 + BK >= K);
        float4 na0, na1, nb0, nb1;
        if (!last) {
            const float* Ap2 = Ap + k0 + BK;
            na0 = *(const float4*)Ap2;
            na1 = *(const float4*)(Ap2 + 8);
            const float* Bp2 = Bp + (size_t)(k0 + BK) * N;
            nb0 = *(const float4*)Bp2;
            nb1 = *(const float4*)(Bp2 + (size_t)8*N);
        }

        #pragma unroll
        for (int ks = 0; ks < 2; ks++) {
            uint32_t af[4][4], bf[4][2];
            #pragma unroll
            for (int mi = 0; mi < 4; mi++) {
                int mb = wm + mi*16;
                af[mi][0] = __float_as_uint(As[buf][ks*8+grp  ][mb+qid  ]);
                af[mi][1] = __float_as_uint(As[buf][ks*8+grp  ][mb+qid+8]);
                af[mi][2] = __float_as_uint(As[buf][ks*8+grp+4][mb+qid  ]);
                af[mi][3] = __float_as_uint(As[buf][ks*8+grp+4][mb+qid+8]);
            }
            #pragma unroll
            for (int nj = 0; nj < 4; nj++) {
                int nb = wn + nj*8;
                bf[nj][0] = __float_as_uint(Bs[buf][ks*8+grp  ][nb+qid]);
                bf[nj][1] = __float_as_uint(Bs[buf][ks*8+grp+4][nb+qid]);
            }
            #pragma unroll
            for (int mi = 0; mi < 4; mi++)
                #pragma unroll
                for (int nj = 0; nj < 4; nj++)
                    mma_tf32(acc[mi][nj][0], acc[mi][nj][1],
                             acc[mi][nj][2], acc[mi][nj][3],
                             af[mi][0], af[mi][1], af[mi][2], af[mi][3],
                             bf[nj][0], bf[nj][1]);
        }
        if (last) break;

        int nb_ = buf ^ 1;
        As[nb_][aCol+0][aRow] = f2tf32(na0.x); As[nb_][aCol+1][aRow] = f2tf32(na0.y);
        As[nb_][aCol+2][aRow] = f2tf32(na0.z); As[nb_][aCol+3][aRow] = f2tf32(na0.w);
        As[nb_][aCol+8][aRow] = f2tf32(na1.x); As[nb_][aCol+9][aRow] = f2tf32(na1.y);
        As[nb_][aCol+10][aRow]= f2tf32(na1.z); As[nb_][aCol+11][aRow]= f2tf32(na1.w);
        float4 c0 = {f2tf32(nb0.x), f2tf32(nb0.y), f2tf32(nb0.z), f2tf32(nb0.w)};
        float4 c1 = {f2tf32(nb1.x), f2tf32(nb1.y), f2tf32(nb1.z), f2tf32(nb1.w)};
        *(float4*)&Bs[nb_][bRow  ][bCol] = c0;
        *(float4*)&Bs[nb_][bRow+8][bCol] = c1;
        __syncthreads();
        buf = nb_;
    }

    // epilogue
    const int row0 = blockIdx.y*128 + wm;
    const int col0 = blockIdx.x*128 + wn;
    #pragma unroll
    for (int mi = 0; mi < 4; mi++) {
        #pragma unroll
        for (int nj = 0; nj < 4; nj++) {
            int c = col0 + nj*8 + grp*2;
            float bv0 = bias[c], bv1 = bias[c+1];
            #pragma unroll
            for (int half = 0; half < 2; half++) {
                int r = row0 + mi*16 + qid + half*8;
                float v0 = acc[mi][nj][half*2+0] + bv0;
                float v1 = acc[mi][nj][half*2+1] + bv1;
                size_t off = (size_t)r * N + c;
                if (EPI == 1) { v0 = gelu_exact(v0); v1 = gelu_exact(v1); }
                if (EPI == 2) { v0 += res[off]; v1 += res[off+1]; }
                float2 o = {v0, v1};
                *(float2*)&C[off] = o;
            }
        }
    }
}

// ---------------- windowed attention -------------------
__global__ __launch_bounds__(256) void attn_kernel(
    const float* __restrict__ qkv, const float* __restrict__ bias_table,
    float* __restrict__ out)
{
    const int w = blockIdx.x;
    const int h = blockIdx.y;
    __shared__ float sq[WWIN*33];
    __shared__ float sk[WWIN*33];
    __shared__ float sv[WWIN*33];
    __shared__ float ss[WWIN*WWIN];

    const int tid = threadIdx.x;
    for (int i = tid; i < WWIN*HDIM; i += 256) {
        int n = i >> 5, d = i & 31;
        size_t base = ((size_t)w*WWIN + n)*768 + h*HDIM + d;
        sq[n*33 + d] = qkv[base];
        sk[n*33 + d] = qkv[base + 256];
        sv[n*33 + d] = qkv[base + 512];
    }
    __syncthreads();

    const bool lastw = ((w & (NWIN-1)) == NWIN-1);
    for (int idx = tid; idx < WWIN*WWIN; idx += 256) {
        int n = idx / WWIN, mm = idx - n*WWIN;
        const float* qn = &sq[n*33];
        const float* km = &sk[mm*33];
        float acc = 0.0f;
        #pragma unroll
        for (int d = 0; d < HDIM; d++) acc += qn[d]*km[d];
        acc *= 0.17677669529663688f;
        acc += __ldg(&bias_table[(mm - n + WWIN - 1)*NHEAD + h]);
        if (lastw && ((n < SSH) != (mm < SSH))) acc -= 100.0f;
        ss[idx] = acc;
    }
    __syncthreads();

    const int warp = tid >> 5, lane = tid & 31;
    for (int n = warp; n < WWIN; n += 8) {
        float v0 = ss[n*WWIN + lane];
        float v1 = (lane < WWIN-32) ? ss[n*WWIN + 32 + lane] : -1e30f;
        float mx = fmaxf(v0, v1);
        #pragma unroll
        for (int o = 16; o; o >>= 1) mx = fmaxf(mx, __shfl_xor_sync(0xffffffffu, mx, o));
        float e0 = __expf(v0 - mx);
        float e1 = (lane < WWIN-32) ? __expf(v1 - mx) : 0.0f;
        float sm = e0 + e1;
        #pragma unroll
        for (int o = 16; o; o >>= 1) sm += __shfl_xor_sync(0xffffffffu, sm, o);
        float r = 1.0f / sm;
        ss[n*WWIN + lane] = e0 * r;
        if (lane < WWIN-32) ss[n*WWIN + 32 + lane] = e1 * r;
    }
    __syncthreads();

    for (int i = tid; i < WWIN*HDIM; i += 256) {
        int n = i >> 5, d = i & 31;
        const float* pn = &ss[n*WWIN];
        float acc = 0.0f;
        #pragma unroll
        for (int mm = 0; mm < WWIN; mm++) acc += pn[mm]*sv[mm*33 + d];
        out[((size_t)w*WWIN + n)*CDIM + h*HDIM + d] = acc;
    }
}

// ---------------- host-side launch -------------------------
extern "C" void kernel_launch(void* const* d_in, const int* in_sizes, int n_in,
                              void* d_out, int out_size)
{
    const float* x     = (const float*)d_in[0];
    const float* n1g   = (const float*)d_in[1];
    const float* n1b   = (const float*)d_in[2];
    const float* qkv_w = (const float*)d_in[3];
    const float* qkv_b = (const float*)d_in[4];
    const float* bt    = (const float*)d_in[5];
    const float* pw    = (const float*)d_in[6];
    const float* pb    = (const float*)d_in[7];
    const float* n2g   = (const float*)d_in[8];
    const float* n2b   = (const float*)d_in[9];
    const float* f1w   = (const float*)d_in[10];
    const float* f1b   = (const float*)d_in[11];
    const float* f2w   = (const float*)d_in[12];
    const float* f2b   = (const float*)d_in[13];
    float* out = (float*)d_out;

    float *h0, *qkvp, *att, *prj, *x1, *m, *f1;
    cudaGetSymbolAddress((void**)&h0,   g_h0);
    cudaGetSymbolAddress((void**)&qkvp, g_qkv);
    cudaGetSymbolAddress((void**)&att,  g_att);
    cudaGetSymbolAddress((void**)&prj,  g_prj);
    cudaGetSymbolAddress((void**)&x1,   g_x1);
    cudaGetSymbolAddress((void**)&m,    g_m);
    cudaGetSymbolAddress((void**)&f1,   g_f1);

    const int MBLK = NTOK / 128;   // 1344

    ln_roll_kernel<<<NTOK/8, 256>>>(x, n1g, n1b, h0);
    tgemm_kernel<0><<<dim3(768/128,  MBLK), 256>>>(h0,  qkv_w, qkv_b, nullptr, qkvp, NTOK, 768,  256);
    attn_kernel<<<dim3(NBWIN, NHEAD), 256>>>(qkvp, bt, att);
    tgemm_kernel<0><<<dim3(256/128,  MBLK), 256>>>(att, pw,    pb,    nullptr, prj,  NTOK, 256,  256);
    resid_ln2_kernel<<<NTOK/8, 256>>>(x, prj, n2g, n2b, x1, m);
    tgemm_kernel<1><<<dim3(1024/128, MBLK), 256>>>(m,   f1w,   f1b,   nullptr, f1,   NTOK, 1024, 256);
    tgemm_kernel<2><<<dim3(256/128,  MBLK), 256>>>(f1,  f2w,   f2b,   x1,      out,  NTOK, 256,  1024);
}

// round 3
// speedup vs baseline: 2.2940x; 1.1465x over previous
#include <cuda_runtime.h>
#include <cuda_bf16.h>
#include <math.h>
#include <stdint.h>

// ---------------- problem constants ----------------
#define BSZ   64
#define LSEQ  2688
#define CDIM  256
#define WWIN  42
#define SSH   21
#define NHEAD 8
#define HDIM  32
#define NWIN  64
#define MLPH  1024
#define NTOK  (BSZ*LSEQ)    // 172032
#define NBWIN (BSZ*NWIN)    // 4096

typedef __nv_bfloat16  bf16;
typedef __nv_bfloat162 bf162;

// ---------------- scratch ----------------
__device__ bf16  gb_h0 [(size_t)NTOK*CDIM];
__device__ float g_qkv [(size_t)NTOK*3*CDIM];
__device__ bf16  gb_att[(size_t)NTOK*CDIM];
__device__ float g_prj [(size_t)NTOK*CDIM];
__device__ float g_x1  [(size_t)NTOK*CDIM];
__device__ bf16  gb_m  [(size_t)NTOK*CDIM];
__device__ bf16  gb_f1 [(size_t)NTOK*MLPH];
// packed bf16 weights: qkv_w | proj_w | fc1_w | fc2_w
#define WOFF_QKV 0
#define WOFF_P   196608
#define WOFF_F1  262144
#define WOFF_F2  524288
__device__ bf16  gb_w  [786432];

// ---------------- fp32 -> bf16 convert -------------
__global__ __launch_bounds__(256) void cvt_kernel(
    const float4* __restrict__ s, bf162* __restrict__ d, int n4)
{
    int i = blockIdx.x*256 + threadIdx.x;
    if (i < n4) {
        float4 v = s[i];
        d[2*i]   = bf162{__float2bfloat16(v.x), __float2bfloat16(v.y)};
        d[2*i+1] = bf162{__float2bfloat16(v.z), __float2bfloat16(v.w)};
    }
}

// ---------------- LayerNorm (+cyclic shift) -> bf16 ----------
__global__ __launch_bounds__(256) void ln_roll_kernel(
    const float* __restrict__ x, const float* __restrict__ g,
    const float* __restrict__ b, bf16* __restrict__ out)
{
    int token = blockIdx.x * 8 + (threadIdx.x >> 5);
    int lane  = threadIdx.x & 31;
    int bi = token / LSEQ, l = token % LSEQ;
    int src = bi * LSEQ + (l + SSH) % LSEQ;
    const float4* xr = (const float4*)(x + (size_t)src * CDIM);
    float4 v0 = xr[lane], v1 = xr[lane + 32];
    float s  = v0.x+v0.y+v0.z+v0.w + v1.x+v1.y+v1.z+v1.w;
    float ss = v0.x*v0.x+v0.y*v0.y+v0.z*v0.z+v0.w*v0.w
             + v1.x*v1.x+v1.y*v1.y+v1.z*v1.z+v1.w*v1.w;
    #pragma unroll
    for (int o = 16; o; o >>= 1) {
        s  += __shfl_xor_sync(0xffffffffu, s,  o);
        ss += __shfl_xor_sync(0xffffffffu, ss, o);
    }
    float mean = s * (1.0f/CDIM);
    float var  = ss * (1.0f/CDIM) - mean*mean;
    float inv  = rsqrtf(var + 1e-5f);
    float4 g0 = ((const float4*)g)[lane], g1 = ((const float4*)g)[lane+32];
    float4 b0 = ((const float4*)b)[lane], b1 = ((const float4*)b)[lane+32];
    bf162* orow = (bf162*)(out + (size_t)token * CDIM);
    orow[2*lane]      = bf162{__float2bfloat16((v0.x-mean)*inv*g0.x+b0.x),
                              __float2bfloat16((v0.y-mean)*inv*g0.y+b0.y)};
    orow[2*lane+1]    = bf162{__float2bfloat16((v0.z-mean)*inv*g0.z+b0.z),
                              __float2bfloat16((v0.w-mean)*inv*g0.w+b0.w)};
    orow[64+2*lane]   = bf162{__float2bfloat16((v1.x-mean)*inv*g1.x+b1.x),
                              __float2bfloat16((v1.y-mean)*inv*g1.y+b1.y)};
    orow[64+2*lane+1] = bf162{__float2bfloat16((v1.z-mean)*inv*g1.z+b1.z),
                              __float2bfloat16((v1.w-mean)*inv*g1.w+b1.w)};
}

// ------------- residual (reverse shift) + LN2 : x1 fp32, m bf16 -----
__global__ __launch_bounds__(256) void resid_ln2_kernel(
    const float* __restrict__ x,  const float* __restrict__ po,
    const float* __restrict__ g,  const float* __restrict__ b,
    float* __restrict__ x1, bf16* __restrict__ m)
{
    int token = blockIdx.x * 8 + (threadIdx.x >> 5);
    int lane  = threadIdx.x & 31;
    int bi = token / LSEQ, l = token % LSEQ;
    int src = bi * LSEQ + (l - SSH + LSEQ) % LSEQ;
    const float4* xr = (const float4*)(x  + (size_t)token * CDIM);
    const float4* pr = (const float4*)(po + (size_t)src   * CDIM);
    float4 a0 = xr[lane], a1 = xr[lane+32];
    float4 p0 = pr[lane], p1 = pr[lane+32];
    float4 v0, v1;
    v0.x=a0.x+p0.x; v0.y=a0.y+p0.y; v0.z=a0.z+p0.z; v0.w=a0.w+p0.w;
    v1.x=a1.x+p1.x; v1.y=a1.y+p1.y; v1.z=a1.z+p1.z; v1.w=a1.w+p1.w;
    float4* x1r = (float4*)(x1 + (size_t)token * CDIM);
    x1r[lane] = v0; x1r[lane+32] = v1;
    float s  = v0.x+v0.y+v0.z+v0.w + v1.x+v1.y+v1.z+v1.w;
    float ss = v0.x*v0.x+v0.y*v0.y+v0.z*v0.z+v0.w*v0.w
             + v1.x*v1.x+v1.y*v1.y+v1.z*v1.z+v1.w*v1.w;
    #pragma unroll
    for (int o = 16; o; o >>= 1) {
        s  += __shfl_xor_sync(0xffffffffu, s,  o);
        ss += __shfl_xor_sync(0xffffffffu, ss, o);
    }
    float mean = s * (1.0f/CDIM);
    float var  = ss * (1.0f/CDIM) - mean*mean;
    float inv  = rsqrtf(var + 1e-5f);
    float4 g0 = ((const float4*)g)[lane], g1 = ((const float4*)g)[lane+32];
    float4 b0 = ((const float4*)b)[lane], b1 = ((const float4*)b)[lane+32];
    bf162* mr = (bf162*)(m + (size_t)token * CDIM);
    mr[2*lane]      = bf162{__float2bfloat16((v0.x-mean)*inv*g0.x+b0.x),
                            __float2bfloat16((v0.y-mean)*inv*g0.y+b0.y)};
    mr[2*lane+1]    = bf162{__float2bfloat16((v0.z-mean)*inv*g0.z+b0.z),
                            __float2bfloat16((v0.w-mean)*inv*g0.w+b0.w)};
    mr[64+2*lane]   = bf162{__float2bfloat16((v1.x-mean)*inv*g1.x+b1.x),
                            __float2bfloat16((v1.y-mean)*inv*g1.y+b1.y)};
    mr[64+2*lane+1] = bf162{__float2bfloat16((v1.z-mean)*inv*g1.z+b1.z),
                            __float2bfloat16((v1.w-mean)*inv*g1.w+b1.w)};
}

// ---------------- bf16 tensor-core GEMM ---------------------
// 128x128 block, BK=32, cp.async 2-stage, 8 warps (2m x 4n), warp 64x32,
// ldmatrix fragments, mma.m16n8k16.bf16, fp32 accumulate.
// EPI: 0=+bias ; 1=+bias,GELU ; 2=+bias,+res(fp32). OUTBF: C dtype.

__device__ __forceinline__ float gelu_exact(float v) {
    return 0.5f * v * (1.0f + erff(v * 0.70710678118654752f));
}
__device__ __forceinline__ void cpasync16(uint32_t saddr, const void* g) {
    asm volatile("cp.async.cg.shared.global [%0], [%1], 16;\n" :: "r"(saddr), "l"(g));
}
__device__ __forceinline__ void cp_commit() {
    asm volatile("cp.async.commit_group;\n");
}
__device__ __forceinline__ void cp_wait0() {
    asm volatile("cp.async.wait_group 0;\n");
}
__device__ __forceinline__ void ldsm_x4(uint32_t* r, uint32_t a) {
    asm volatile("ldmatrix.sync.aligned.m8n8.x4.shared.b16 {%0,%1,%2,%3}, [%4];"
        : "=r"(r[0]), "=r"(r[1]), "=r"(r[2]), "=r"(r[3]) : "r"(a));
}
__device__ __forceinline__ void ldsm_x4t(uint32_t* r, uint32_t a) {
    asm volatile("ldmatrix.sync.aligned.m8n8.x4.trans.shared.b16 {%0,%1,%2,%3}, [%4];"
        : "=r"(r[0]), "=r"(r[1]), "=r"(r[2]), "=r"(r[3]) : "r"(a));
}
__device__ __forceinline__ void mma_bf16(
    float& c0, float& c1, float& c2, float& c3,
    uint32_t a0, uint32_t a1, uint32_t a2, uint32_t a3,
    uint32_t b0, uint32_t b1)
{
    asm volatile(
        "mma.sync.aligned.m16n8k16.row.col.f32.bf16.bf16.f32 "
        "{%0,%1,%2,%3}, {%4,%5,%6,%7}, {%8,%9}, {%0,%1,%2,%3};\n"
        : "+f"(c0), "+f"(c1), "+f"(c2), "+f"(c3)
        : "r"(a0), "r"(a1), "r"(a2), "r"(a3), "r"(b0), "r"(b1));
}

#define BKK 32
#define LDA 40     // bf16 elems per As row (32 + 8 pad) -> 80B, 16B-multiple
#define LDB 136    // bf16 elems per Bs row (128 + 8 pad) -> 272B

template<int EPI, int OUTBF>
__global__ __launch_bounds__(256) void bgemm_kernel(
    const bf16* __restrict__ A, const bf16* __restrict__ Bw,
    const float* __restrict__ bias, const float* __restrict__ res,
    void* __restrict__ Cv, int M, int N, int K)
{
    __shared__ __align__(16) bf16 As[2][128*LDA];
    __shared__ __align__(16) bf16 Bs[2][BKK*LDB];

    const int tid  = threadIdx.x;
    const int warp = tid >> 5, lane = tid & 31;
    const int wm  = (warp >> 2) * 64;
    const int wn  = (warp & 3) * 32;
    const int grp = lane & 3;
    const int qid = lane >> 2;

    // global load mapping (per thread: 2x16B for A, 2x16B for B)
    const int arow = tid >> 1, acol = (tid & 1) * 16;
    const int brow = tid >> 3, bcol = (tid & 7) * 16;
    const bf16* Ag = A  + (size_t)(blockIdx.y*128 + arow) * K + acol;
    const bf16* Bg = Bw + (size_t)brow * N + blockIdx.x*128 + bcol;

    uint32_t asBase0 = (uint32_t)__cvta_generic_to_shared(&As[0][0]);
    uint32_t asBase1 = (uint32_t)__cvta_generic_to_shared(&As[1][0]);
    uint32_t bsBase0 = (uint32_t)__cvta_generic_to_shared(&Bs[0][0]);
    uint32_t bsBase1 = (uint32_t)__cvta_generic_to_shared(&Bs[1][0]);
    const uint32_t asOff = (uint32_t)(arow*LDA + acol) * 2;
    const uint32_t bsOff = (uint32_t)(brow*LDB + bcol) * 2;

    float acc[4][4][4];
    #pragma unroll
    for (int i = 0; i < 4; i++)
        #pragma unroll
        for (int j = 0; j < 4; j++)
            #pragma unroll
            for (int t = 0; t < 4; t++) acc[i][j][t] = 0.0f;

    const int NIT = K / BKK;

    // prologue: stage for iter 0 into slot 0
    cpasync16(asBase0 + asOff,      Ag);
    cpasync16(asBase0 + asOff + 16, Ag + 8);
    cpasync16(bsBase0 + bsOff,      Bg);
    cpasync16(bsBase0 + bsOff + 16, Bg + 8);
    cp_commit();

    for (int it = 0; it < NIT; it++) {
        cp_wait0();
        __syncthreads();

        // issue next stage (overlaps compute below)
        if (it + 1 < NIT) {
            const int k0 = (it + 1) * BKK;
            uint32_t asB = ((it+1) & 1) ? asBase1 : asBase0;
            uint32_t bsB = ((it+1) & 1) ? bsBase1 : bsBase0;
            const bf16* Ag2 = Ag + k0;
            const bf16* Bg2 = Bg + (size_t)k0 * N;
            cpasync16(asB + asOff,      Ag2);
            cpasync16(asB + asOff + 16, Ag2 + 8);
            cpasync16(bsB + bsOff,      Bg2);
            cpasync16(bsB + bsOff + 16, Bg2 + 8);
        }
        cp_commit();

        uint32_t asB = (it & 1) ? asBase1 : asBase0;
        uint32_t bsB = (it & 1) ? bsBase1 : bsBase0;

        #pragma unroll
        for (int ks = 0; ks < 2; ks++) {
            const int kb = ks * 16;
            uint32_t af[4][4];
            #pragma unroll
            for (int mi = 0; mi < 4; mi++) {
                int row = wm + mi*16 + (lane & 15);
                uint32_t addr = asB + ((uint32_t)(row*LDA + kb + (lane >> 4)*8)) * 2;
                ldsm_x4(af[mi], addr);
            }
            uint32_t bfr[2][4];
            #pragma unroll
            for (int gj = 0; gj < 2; gj++) {
                int krow = kb + (lane & 7) + ((lane >> 3) & 1) * 8;
                int col  = wn + gj*16 + (lane >> 4) * 8;
                uint32_t addr = bsB + ((uint32_t)(krow*LDB + col)) * 2;
                ldsm_x4t(bfr[gj], addr);
            }
            #pragma unroll
            for (int mi = 0; mi < 4; mi++)
                #pragma unroll
                for (int nj = 0; nj < 4; nj++)
                    mma_bf16(acc[mi][nj][0], acc[mi][nj][1],
                             acc[mi][nj][2], acc[mi][nj][3],
                             af[mi][0], af[mi][1], af[mi][2], af[mi][3],
                             bfr[nj >> 1][(nj & 1)*2], bfr[nj >> 1][(nj & 1)*2 + 1]);
        }
        __syncthreads();
    }

    // epilogue
    const int row0 = blockIdx.y*128 + wm;
    const int col0 = blockIdx.x*128 + wn;
    #pragma unroll
    for (int mi = 0; mi < 4; mi++) {
        #pragma unroll
        for (int nj = 0; nj < 4; nj++) {
            int c = col0 + nj*8 + grp*2;
            float bv0 = bias[c], bv1 = bias[c+1];
            #pragma unroll
            for (int half = 0; half < 2; half++) {
                int r = row0 + mi*16 + qid + half*8;
                float v0 = acc[mi][nj][half*2+0] + bv0;
                float v1 = acc[mi][nj][half*2+1] + bv1;
                size_t off = (size_t)r * N + c;
                if (EPI == 1) { v0 = gelu_exact(v0); v1 = gelu_exact(v1); }
                if (EPI == 2) { v0 += res[off]; v1 += res[off+1]; }
                if (OUTBF) {
                    bf162 o = {__float2bfloat16(v0), __float2bfloat16(v1)};
                    *(bf162*)((bf16*)Cv + off) = o;
                } else {
                    float2 o = {v0, v1};
                    *(float2*)((float*)Cv + off) = o;
                }
            }
        }
    }
}

// ---------------- windowed attention (fp32 math, bf16 out) ------------
__global__ __launch_bounds__(256) void attn_kernel(
    const float* __restrict__ qkv, const float* __restrict__ bias_table,
    bf16* __restrict__ out)
{
    const int w = blockIdx.x;
    const int h = blockIdx.y;
    __shared__ float sq[44*33];
    __shared__ float sk[44*33];
    __shared__ float sv[44*33];
    __shared__ float ss[WWIN*WWIN];

    const int tid = threadIdx.x;
    for (int i = tid; i < WWIN*HDIM; i += 256) {
        int n = i >> 5, d = i & 31;
        size_t base = ((size_t)w*WWIN + n)*768 + h*HDIM + d;
        sq[n*33 + d] = qkv[base];
        sk[n*33 + d] = qkv[base + 256];
        sv[n*33 + d] = qkv[base + 512];
    }
    // zero pad rows 42,43 of sk so 4-wide tiles can overread safely
    for (int i = tid; i < 2*HDIM; i += 256) {
        int n = 42 + (i >> 5), d = i & 31;
        sk[n*33 + d] = 0.0f;
    }
    __syncthreads();

    const bool lastw = ((w & (NWIN-1)) == NWIN-1);
    // QK^T: each unit computes 4 consecutive mm for one n
    for (int u = tid; u < WWIN*11; u += 256) {
        int n = u / 11, m0 = (u % 11) * 4;
        const float* qn = &sq[n*33];
        const float* kp = &sk[m0*33];
        float a0=0.f, a1=0.f, a2=0.f, a3=0.f;
        #pragma unroll
        for (int d = 0; d < HDIM; d++) {
            float qv = qn[d];
            a0 += qv * kp[d];
            a1 += qv * kp[33+d];
            a2 += qv * kp[66+d];
            a3 += qv * kp[99+d];
        }
        float av[4] = {a0, a1, a2, a3};
        #pragma unroll
        for (int j = 0; j < 4; j++) {
            int mm = m0 + j;
            if (mm < WWIN) {
                float acc = av[j] * 0.17677669529663688f
                          + __ldg(&bias_table[(mm - n + WWIN - 1)*NHEAD + h]);
                if (lastw && ((n < SSH) != (mm < SSH))) acc -= 100.0f;
                ss[n*WWIN + mm] = acc;
            }
        }
    }
    __syncthreads();

    const int warp = tid >> 5, lane = tid & 31;
    for (int n = warp; n < WWIN; n += 8) {
        float v0 = ss[n*WWIN + lane];
        float v1 = (lane < WWIN-32) ? ss[n*WWIN + 32 + lane] : -1e30f;
        float mx = fmaxf(v0, v1);
        #pragma unroll
        for (int o = 16; o; o >>= 1) mx = fmaxf(mx, __shfl_xor_sync(0xffffffffu, mx, o));
        float e0 = __expf(v0 - mx);
        float e1 = (lane < WWIN-32) ? __expf(v1 - mx) : 0.0f;
        float sm = e0 + e1;
        #pragma unroll
        for (int o = 16; o; o >>= 1) sm += __shfl_xor_sync(0xffffffffu, sm, o);
        float r = 1.0f / sm;
        ss[n*WWIN + lane] = e0 * r;
        if (lane < WWIN-32) ss[n*WWIN + 32 + lane] = e1 * r;
    }
    __syncthreads();

    // PV: each unit computes 4 consecutive d for one n
    for (int u = tid; u < WWIN*8; u += 256) {
        int n = u >> 3, d0 = (u & 7) * 4;
        const float* pn = &ss[n*WWIN];
        float a0=0.f, a1=0.f, a2=0.f, a3=0.f;
        #pragma unroll
        for (int mm = 0; mm < WWIN; mm++) {
            float p = pn[mm];
            const float* vr = &sv[mm*33 + d0];
            a0 += p*vr[0]; a1 += p*vr[1]; a2 += p*vr[2]; a3 += p*vr[3];
        }
        size_t base = ((size_t)w*WWIN + n)*CDIM + h*HDIM + d0;
        bf162 o0 = {__float2bfloat16(a0), __float2bfloat16(a1)};
        bf162 o1 = {__float2bfloat16(a2), __float2bfloat16(a3)};
        *(bf162*)(out + base)     = o0;
        *(bf162*)(out + base + 2) = o1;
    }
}

// ---------------- host-side launch --------------------------
extern "C" void kernel_launch(void* const* d_in, const int* in_sizes, int n_in,
                              void* d_out, int out_size)
{
    const float* x     = (const float*)d_in[0];
    const float* n1g   = (const float*)d_in[1];
    const float* n1b   = (const float*)d_in[2];
    const float* qkv_w = (const float*)d_in[3];
    const float* qkv_b = (const float*)d_in[4];
    const float* bt    = (const float*)d_in[5];
    const float* pw    = (const float*)d_in[6];
    const float* pb    = (const float*)d_in[7];
    const float* n2g   = (const float*)d_in[8];
    const float* n2b   = (const float*)d_in[9];
    const float* f1w   = (const float*)d_in[10];
    const float* f1b   = (const float*)d_in[11];
    const float* f2w   = (const float*)d_in[12];
    const float* f2b   = (const float*)d_in[13];
    float* out = (float*)d_out;

    bf16 *h0b, *attb, *mb, *f1b_buf, *wb;
    float *qkvp, *prj, *x1;
    cudaGetSymbolAddress((void**)&h0b,    gb_h0);
    cudaGetSymbolAddress((void**)&qkvp,   g_qkv);
    cudaGetSymbolAddress((void**)&attb,   gb_att);
    cudaGetSymbolAddress((void**)&prj,    g_prj);
    cudaGetSymbolAddress((void**)&x1,     g_x1);
    cudaGetSymbolAddress((void**)&mb,     gb_m);
    cudaGetSymbolAddress((void**)&f1b_buf,gb_f1);
    cudaGetSymbolAddress((void**)&wb,     gb_w);

    // weight conversion (tiny)
    cvt_kernel<<<192, 256>>>((const float4*)qkv_w, (bf162*)(wb + WOFF_QKV), 49152);
    cvt_kernel<<<64,  256>>>((const float4*)pw,    (bf162*)(wb + WOFF_P),   16384);
    cvt_kernel<<<256, 256>>>((const float4*)f1w,   (bf162*)(wb + WOFF_F1),  65536);
    cvt_kernel<<<256, 256>>>((const float4*)f2w,   (bf162*)(wb + WOFF_F2),  65536);

    const int MBLK = NTOK / 128;   // 1344

    // 1) LN1 + roll(-S) -> bf16
    ln_roll_kernel<<<NTOK/8, 256>>>(x, n1g, n1b, h0b);
    // 2) QKV GEMM (fp32 out for attention)
    bgemm_kernel<0,0><<<dim3(6, MBLK), 256>>>(h0b, wb + WOFF_QKV, qkv_b, nullptr, qkvp, NTOK, 768, 256);
    // 3) windowed attention -> bf16
    attn_kernel<<<dim3(NBWIN, NHEAD), 256>>>(qkvp, bt, attb);
    // 4) proj GEMM (fp32 out for residual)
    bgemm_kernel<0,0><<<dim3(2, MBLK), 256>>>(attb, wb + WOFF_P, pb, nullptr, prj, NTOK, 256, 256);
    // 5) residual (roll +S) + LN2 : x1 fp32, m bf16
    resid_ln2_kernel<<<NTOK/8, 256>>>(x, prj, n2g, n2b, x1, mb);
    // 6) FC1 + GELU -> bf16
    bgemm_kernel<1,1><<<dim3(8, MBLK), 256>>>(mb, wb + WOFF_F1, f1b, nullptr, f1b_buf, NTOK, 1024, 256);
    // 7) FC2 + residual -> fp32 out
    bgemm_kernel<2,0><<<dim3(2, MBLK), 256>>>(f1b_buf, wb + WOFF_F2, f2b, x1, out, NTOK, 256, 1024);
}

// round 4
// speedup vs baseline: 2.5097x; 1.0940x over previous
#include <cuda_runtime.h>
#include <cuda_bf16.h>
#include <math.h>
#include <stdint.h>

// ---------------- problem constants ----------------
#define BSZ   64
#define LSEQ  2688
#define CDIM  256
#define WWIN  42
#define SSH   21
#define NHEAD 8
#define HDIM  32
#define NWIN  64
#define MLPH  1024
#define NTOK  (BSZ*LSEQ)    // 172032
#define NBWIN (BSZ*NWIN)    // 4096

typedef __nv_bfloat16  bf16;
typedef __nv_bfloat162 bf162;

// ---------------- scratch ----------------
__device__ bf16  gb_h0 [(size_t)NTOK*CDIM];
__device__ bf16  gb_qkv[(size_t)NTOK*3*CDIM];
__device__ bf16  gb_att[(size_t)NTOK*CDIM];
__device__ float g_prj [(size_t)NTOK*CDIM];
__device__ float g_x1  [(size_t)NTOK*CDIM];
__device__ bf16  gb_m  [(size_t)NTOK*CDIM];
__device__ bf16  gb_f1 [(size_t)NTOK*MLPH];
#define WOFF_QKV 0
#define WOFF_P   196608
#define WOFF_F1  262144
#define WOFF_F2  524288
__device__ bf16  gb_w  [786432];

// ---------------- fp32 -> bf16 convert -------------
__global__ __launch_bounds__(256) void cvt_kernel(
    const float4* __restrict__ s, bf162* __restrict__ d, int n4)
{
    int i = blockIdx.x*256 + threadIdx.x;
    if (i < n4) {
        float4 v = s[i];
        d[2*i]   = bf162{__float2bfloat16(v.x), __float2bfloat16(v.y)};
        d[2*i+1] = bf162{__float2bfloat16(v.z), __float2bfloat16(v.w)};
    }
}

// ---------------- LayerNorm (+cyclic shift) -> bf16 ----------
__global__ __launch_bounds__(256) void ln_roll_kernel(
    const float* __restrict__ x, const float* __restrict__ g,
    const float* __restrict__ b, bf16* __restrict__ out)
{
    int token = blockIdx.x * 8 + (threadIdx.x >> 5);
    int lane  = threadIdx.x & 31;
    int bi = token / LSEQ, l = token % LSEQ;
    int src = bi * LSEQ + (l + SSH) % LSEQ;
    const float4* xr = (const float4*)(x + (size_t)src * CDIM);
    float4 v0 = xr[lane], v1 = xr[lane + 32];
    float s  = v0.x+v0.y+v0.z+v0.w + v1.x+v1.y+v1.z+v1.w;
    float ss = v0.x*v0.x+v0.y*v0.y+v0.z*v0.z+v0.w*v0.w
             + v1.x*v1.x+v1.y*v1.y+v1.z*v1.z+v1.w*v1.w;
    #pragma unroll
    for (int o = 16; o; o >>= 1) {
        s  += __shfl_xor_sync(0xffffffffu, s,  o);
        ss += __shfl_xor_sync(0xffffffffu, ss, o);
    }
    float mean = s * (1.0f/CDIM);
    float var  = ss * (1.0f/CDIM) - mean*mean;
    float inv  = rsqrtf(var + 1e-5f);
    float4 g0 = ((const float4*)g)[lane], g1 = ((const float4*)g)[lane+32];
    float4 b0 = ((const float4*)b)[lane], b1 = ((const float4*)b)[lane+32];
    bf162* orow = (bf162*)(out + (size_t)token * CDIM);
    orow[2*lane]      = bf162{__float2bfloat16((v0.x-mean)*inv*g0.x+b0.x),
                              __float2bfloat16((v0.y-mean)*inv*g0.y+b0.y)};
    orow[2*lane+1]    = bf162{__float2bfloat16((v0.z-mean)*inv*g0.z+b0.z),
                              __float2bfloat16((v0.w-mean)*inv*g0.w+b0.w)};
    orow[64+2*lane]   = bf162{__float2bfloat16((v1.x-mean)*inv*g1.x+b1.x),
                              __float2bfloat16((v1.y-mean)*inv*g1.y+b1.y)};
    orow[64+2*lane+1] = bf162{__float2bfloat16((v1.z-mean)*inv*g1.z+b1.z),
                              __float2bfloat16((v1.w-mean)*inv*g1.w+b1.w)};
}

// ------------- residual (reverse shift) + LN2 : x1 fp32, m bf16 -----
__global__ __launch_bounds__(256) void resid_ln2_kernel(
    const float* __restrict__ x,  const float* __restrict__ po,
    const float* __restrict__ g,  const float* __restrict__ b,
    float* __restrict__ x1, bf16* __restrict__ m)
{
    int token = blockIdx.x * 8 + (threadIdx.x >> 5);
    int lane  = threadIdx.x & 31;
    int bi = token / LSEQ, l = token % LSEQ;
    int src = bi * LSEQ + (l - SSH + LSEQ) % LSEQ;
    const float4* xr = (const float4*)(x  + (size_t)token * CDIM);
    const float4* pr = (const float4*)(po + (size_t)src   * CDIM);
    float4 a0 = xr[lane], a1 = xr[lane+32];
    float4 p0 = pr[lane], p1 = pr[lane+32];
    float4 v0, v1;
    v0.x=a0.x+p0.x; v0.y=a0.y+p0.y; v0.z=a0.z+p0.z; v0.w=a0.w+p0.w;
    v1.x=a1.x+p1.x; v1.y=a1.y+p1.y; v1.z=a1.z+p1.z; v1.w=a1.w+p1.w;
    float4* x1r = (float4*)(x1 + (size_t)token * CDIM);
    x1r[lane] = v0; x1r[lane+32] = v1;
    float s  = v0.x+v0.y+v0.z+v0.w + v1.x+v1.y+v1.z+v1.w;
    float ss = v0.x*v0.x+v0.y*v0.y+v0.z*v0.z+v0.w*v0.w
             + v1.x*v1.x+v1.y*v1.y+v1.z*v1.z+v1.w*v1.w;
    #pragma unroll
    for (int o = 16; o; o >>= 1) {
        s  += __shfl_xor_sync(0xffffffffu, s,  o);
        ss += __shfl_xor_sync(0xffffffffu, ss, o);
    }
    float mean = s * (1.0f/CDIM);
    float var  = ss * (1.0f/CDIM) - mean*mean;
    float inv  = rsqrtf(var + 1e-5f);
    float4 g0 = ((const float4*)g)[lane], g1 = ((const float4*)g)[lane+32];
    float4 b0 = ((const float4*)b)[lane], b1 = ((const float4*)b)[lane+32];
    bf162* mr = (bf162*)(m + (size_t)token * CDIM);
    mr[2*lane]      = bf162{__float2bfloat16((v0.x-mean)*inv*g0.x+b0.x),
                            __float2bfloat16((v0.y-mean)*inv*g0.y+b0.y)};
    mr[2*lane+1]    = bf162{__float2bfloat16((v0.z-mean)*inv*g0.z+b0.z),
                            __float2bfloat16((v0.w-mean)*inv*g0.w+b0.w)};
    mr[64+2*lane]   = bf162{__float2bfloat16((v1.x-mean)*inv*g1.x+b1.x),
                            __float2bfloat16((v1.y-mean)*inv*g1.y+b1.y)};
    mr[64+2*lane+1] = bf162{__float2bfloat16((v1.z-mean)*inv*g1.z+b1.z),
                            __float2bfloat16((v1.w-mean)*inv*g1.w+b1.w)};
}

// ---------------- bf16 tensor-core GEMM ---------------------
// 128x128 block, BK=32, 3-stage cp.async pipeline (wait_group 1,
// single __syncthreads per iter), 8 warps (2m x 4n), warp 64x32,
// ldmatrix fragments, mma.m16n8k16.bf16, fp32 accumulate.

__device__ __forceinline__ float gelu_exact(float v) {
    return 0.5f * v * (1.0f + erff(v * 0.70710678118654752f));
}
__device__ __forceinline__ void cpasync16(uint32_t saddr, const void* g) {
    asm volatile("cp.async.cg.shared.global [%0], [%1], 16;\n" :: "r"(saddr), "l"(g));
}
__device__ __forceinline__ void cp_commit() {
    asm volatile("cp.async.commit_group;\n");
}
__device__ __forceinline__ void cp_wait1() {
    asm volatile("cp.async.wait_group 1;\n");
}
__device__ __forceinline__ void ldsm_x4(uint32_t* r, uint32_t a) {
    asm volatile("ldmatrix.sync.aligned.m8n8.x4.shared.b16 {%0,%1,%2,%3}, [%4];"
        : "=r"(r[0]), "=r"(r[1]), "=r"(r[2]), "=r"(r[3]) : "r"(a));
}
__device__ __forceinline__ void ldsm_x4t(uint32_t* r, uint32_t a) {
    asm volatile("ldmatrix.sync.aligned.m8n8.x4.trans.shared.b16 {%0,%1,%2,%3}, [%4];"
        : "=r"(r[0]), "=r"(r[1]), "=r"(r[2]), "=r"(r[3]) : "r"(a));
}
__device__ __forceinline__ void mma_bf16(
    float& c0, float& c1, float& c2, float& c3,
    uint32_t a0, uint32_t a1, uint32_t a2, uint32_t a3,
    uint32_t b0, uint32_t b1)
{
    asm volatile(
        "mma.sync.aligned.m16n8k16.row.col.f32.bf16.bf16.f32 "
        "{%0,%1,%2,%3}, {%4,%5,%6,%7}, {%8,%9}, {%0,%1,%2,%3};\n"
        : "+f"(c0), "+f"(c1), "+f"(c2), "+f"(c3)
        : "r"(a0), "r"(a1), "r"(a2), "r"(a3), "r"(b0), "r"(b1));
}

#define BKK  32
#define LDA  40     // 32 + 8 pad (bf16)
#define LDB  136    // 128 + 8 pad (bf16)
#define ASZ  (128*LDA*2)   // bytes per A stage
#define BSZB (BKK*LDB*2)   // bytes per B stage

template<int EPI, int OUTBF>
__global__ __launch_bounds__(256) void bgemm_kernel(
    const bf16* __restrict__ A, const bf16* __restrict__ Bw,
    const float* __restrict__ bias, const float* __restrict__ res,
    void* __restrict__ Cv, int M, int N, int K)
{
    __shared__ __align__(16) bf16 As[3][128*LDA];
    __shared__ __align__(16) bf16 Bs[3][BKK*LDB];

    const int tid  = threadIdx.x;
    const int warp = tid >> 5, lane = tid & 31;
    const int wm  = (warp >> 2) * 64;
    const int wn  = (warp & 3) * 32;
    const int grp = lane & 3;
    const int qid = lane >> 2;

    const int arow = tid >> 1, acol = (tid & 1) * 16;
    const int brow = tid >> 3, bcol = (tid & 7) * 16;
    const bf16* Ag = A  + (size_t)(blockIdx.y*128 + arow) * K + acol;
    const bf16* Bg = Bw + (size_t)brow * N + blockIdx.x*128 + bcol;

    const uint32_t asBase = (uint32_t)__cvta_generic_to_shared(&As[0][0]);
    const uint32_t bsBase = (uint32_t)__cvta_generic_to_shared(&Bs[0][0]);
    const uint32_t asOff = (uint32_t)(arow*LDA + acol) * 2;
    const uint32_t bsOff = (uint32_t)(brow*LDB + bcol) * 2;

    float acc[4][4][4];
    #pragma unroll
    for (int i = 0; i < 4; i++)
        #pragma unroll
        for (int j = 0; j < 4; j++)
            #pragma unroll
            for (int t = 0; t < 4; t++) acc[i][j][t] = 0.0f;

    const int NIT = K / BKK;

    // prologue: stages 0,1
    #pragma unroll
    for (int s = 0; s < 2; s++) {
        const int k0 = s * BKK;
        uint32_t aB = asBase + s*ASZ, bB = bsBase + s*BSZB;
        cpasync16(aB + asOff,      Ag + k0);
        cpasync16(aB + asOff + 16, Ag + k0 + 8);
        cpasync16(bB + bsOff,      Bg + (size_t)k0*N);
        cpasync16(bB + bsOff + 16, Bg + (size_t)k0*N + 8);
        cp_commit();
    }

    int buf = 0;
    for (int it = 0; it < NIT; it++) {
        cp_wait1();
        __syncthreads();

        // issue stage it+2 into buffer consumed at iter it-1
        if (it + 2 < NIT) {
            const int k0 = (it + 2) * BKK;
            int nb = (buf + 2 >= 3) ? buf - 1 : buf + 2;
            uint32_t aB = asBase + nb*ASZ, bB = bsBase + nb*BSZB;
            cpasync16(aB + asOff,      Ag + k0);
            cpasync16(aB + asOff + 16, Ag + k0 + 8);
            cpasync16(bB + bsOff,      Bg + (size_t)k0*N);
            cpasync16(bB + bsOff + 16, Bg + (size_t)k0*N + 8);
        }
        cp_commit();

        uint32_t asB = asBase + buf*ASZ;
        uint32_t bsB = bsBase + buf*BSZB;

        #pragma unroll
        for (int ks = 0; ks < 2; ks++) {
            const int kb = ks * 16;
            uint32_t af[4][4];
            #pragma unroll
            for (int mi = 0; mi < 4; mi++) {
                int row = wm + mi*16 + (lane & 15);
                uint32_t addr = asB + ((uint32_t)(row*LDA + kb + (lane >> 4)*8)) * 2;
                ldsm_x4(af[mi], addr);
            }
            uint32_t bfr[2][4];
            #pragma unroll
            for (int gj = 0; gj < 2; gj++) {
                int krow = kb + (lane & 7) + ((lane >> 3) & 1) * 8;
                int col  = wn + gj*16 + (lane >> 4) * 8;
                uint32_t addr = bsB + ((uint32_t)(krow*LDB + col)) * 2;
                ldsm_x4t(bfr[gj], addr);
            }
            #pragma unroll
            for (int mi = 0; mi < 4; mi++)
                #pragma unroll
                for (int nj = 0; nj < 4; nj++)
                    mma_bf16(acc[mi][nj][0], acc[mi][nj][1],
                             acc[mi][nj][2], acc[mi][nj][3],
                             af[mi][0], af[mi][1], af[mi][2], af[mi][3],
                             bfr[nj >> 1][(nj & 1)*2], bfr[nj >> 1][(nj & 1)*2 + 1]);
        }
        buf = (buf + 1 >= 3) ? 0 : buf + 1;
    }

    // epilogue
    const int row0 = blockIdx.y*128 + wm;
    const int col0 = blockIdx.x*128 + wn;
    #pragma unroll
    for (int mi = 0; mi < 4; mi++) {
        #pragma unroll
        for (int nj = 0; nj < 4; nj++) {
            int c = col0 + nj*8 + grp*2;
            float bv0 = bias[c], bv1 = bias[c+1];
            #pragma unroll
            for (int half = 0; half < 2; half++) {
                int r = row0 + mi*16 + qid + half*8;
                float v0 = acc[mi][nj][half*2+0] + bv0;
                float v1 = acc[mi][nj][half*2+1] + bv1;
                size_t off = (size_t)r * N + c;
                if (EPI == 1) { v0 = gelu_exact(v0); v1 = gelu_exact(v1); }
                if (EPI == 2) { v0 += res[off]; v1 += res[off+1]; }
                if (OUTBF) {
                    bf162 o = {__float2bfloat16(v0), __float2bfloat16(v1)};
                    *(bf162*)((bf16*)Cv + off) = o;
                } else {
                    float2 o = {v0, v1};
                    *(float2*)((float*)Cv + off) = o;
                }
            }
        }
    }
}

// ---------------- windowed attention (bf16 in, fp32 math, bf16 out) ---
__global__ __launch_bounds__(256) void attn_kernel(
    const bf16* __restrict__ qkv, const float* __restrict__ bias_table,
    bf16* __restrict__ out)
{
    const int w = blockIdx.x;
    const int h = blockIdx.y;
    __shared__ float sq[44*33];
    __shared__ float sk[44*33];
    __shared__ float sv[44*33];
    __shared__ float ss[WWIN*WWIN];

    const int tid = threadIdx.x;
    // load bf16 pairs -> fp32 smem
    for (int i = tid; i < WWIN*16; i += 256) {
        int n = i >> 4, d2 = (i & 15) * 2;
        size_t base = ((size_t)w*WWIN + n)*768 + h*HDIM + d2;
        float2 q2 = __bfloat1622float2(*(const bf162*)(qkv + base));
        float2 k2 = __bfloat1622float2(*(const bf162*)(qkv + base + 256));
        float2 v2 = __bfloat1622float2(*(const bf162*)(qkv + base + 512));
        sq[n*33 + d2] = q2.x; sq[n*33 + d2 + 1] = q2.y;
        sk[n*33 + d2] = k2.x; sk[n*33 + d2 + 1] = k2.y;
        sv[n*33 + d2] = v2.x; sv[n*33 + d2 + 1] = v2.y;
    }
    for (int i = tid; i < 2*HDIM; i += 256) {
        int n = 42 + (i >> 5), d = i & 31;
        sk[n*33 + d] = 0.0f;
    }
    __syncthreads();

    const bool lastw = ((w & (NWIN-1)) == NWIN-1);
    for (int u = tid; u < WWIN*11; u += 256) {
        int n = u / 11, m0 = (u % 11) * 4;
        const float* qn = &sq[n*33];
        const float* kp = &sk[m0*33];
        float a0=0.f, a1=0.f, a2=0.f, a3=0.f;
        #pragma unroll
        for (int d = 0; d < HDIM; d++) {
            float qv = qn[d];
            a0 += qv * kp[d];
            a1 += qv * kp[33+d];
            a2 += qv * kp[66+d];
            a3 += qv * kp[99+d];
        }
        float av[4] = {a0, a1, a2, a3};
        #pragma unroll
        for (int j = 0; j < 4; j++) {
            int mm = m0 + j;
            if (mm < WWIN) {
                float acc = av[j] * 0.17677669529663688f
                          + __ldg(&bias_table[(mm - n + WWIN - 1)*NHEAD + h]);
                if (lastw && ((n < SSH) != (mm < SSH))) acc -= 100.0f;
                ss[n*WWIN + mm] = acc;
            }
        }
    }
    __syncthreads();

    const int warp = tid >> 5, lane = tid & 31;
    for (int n = warp; n < WWIN; n += 8) {
        float v0 = ss[n*WWIN + lane];
        float v1 = (lane < WWIN-32) ? ss[n*WWIN + 32 + lane] : -1e30f;
        float mx = fmaxf(v0, v1);
        #pragma unroll
        for (int o = 16; o; o >>= 1) mx = fmaxf(mx, __shfl_xor_sync(0xffffffffu, mx, o));
        float e0 = __expf(v0 - mx);
        float e1 = (lane < WWIN-32) ? __expf(v1 - mx) : 0.0f;
        float sm = e0 + e1;
        #pragma unroll
        for (int o = 16; o; o >>= 1) sm += __shfl_xor_sync(0xffffffffu, sm, o);
        float r = 1.0f / sm;
        ss[n*WWIN + lane] = e0 * r;
        if (lane < WWIN-32) ss[n*WWIN + 32 + lane] = e1 * r;
    }
    __syncthreads();

    for (int u = tid; u < WWIN*8; u += 256) {
        int n = u >> 3, d0 = (u & 7) * 4;
        const float* pn = &ss[n*WWIN];
        float a0=0.f, a1=0.f, a2=0.f, a3=0.f;
        #pragma unroll
        for (int mm = 0; mm < WWIN; mm++) {
            float p = pn[mm];
            const float* vr = &sv[mm*33 + d0];
            a0 += p*vr[0]; a1 += p*vr[1]; a2 += p*vr[2]; a3 += p*vr[3];
        }
        size_t base = ((size_t)w*WWIN + n)*CDIM + h*HDIM + d0;
        bf162 o0 = {__float2bfloat16(a0), __float2bfloat16(a1)};
        bf162 o1 = {__float2bfloat16(a2), __float2bfloat16(a3)};
        *(bf162*)(out + base)     = o0;
        *(bf162*)(out + base + 2) = o1;
    }
}

// ---------------- host-side launch --------------------------
extern "C" void kernel_launch(void* const* d_in, const int* in_sizes, int n_in,
                              void* d_out, int out_size)
{
    const float* x     = (const float*)d_in[0];
    const float* n1g   = (const float*)d_in[1];
    const float* n1b   = (const float*)d_in[2];
    const float* qkv_w = (const float*)d_in[3];
    const float* qkv_b = (const float*)d_in[4];
    const float* bt    = (const float*)d_in[5];
    const float* pw    = (const float*)d_in[6];
    const float* pb    = (const float*)d_in[7];
    const float* n2g   = (const float*)d_in[8];
    const float* n2b   = (const float*)d_in[9];
    const float* f1w   = (const float*)d_in[10];
    const float* f1b   = (const float*)d_in[11];
    const float* f2w   = (const float*)d_in[12];
    const float* f2b   = (const float*)d_in[13];
    float* out = (float*)d_out;

    bf16 *h0b, *qkvb, *attb, *mb, *f1b_buf, *wb;
    float *prj, *x1;
    cudaGetSymbolAddress((void**)&h0b,    gb_h0);
    cudaGetSymbolAddress((void**)&qkvb,   gb_qkv);
    cudaGetSymbolAddress((void**)&attb,   gb_att);
    cudaGetSymbolAddress((void**)&prj,    g_prj);
    cudaGetSymbolAddress((void**)&x1,     g_x1);
    cudaGetSymbolAddress((void**)&mb,     gb_m);
    cudaGetSymbolAddress((void**)&f1b_buf,gb_f1);
    cudaGetSymbolAddress((void**)&wb,     gb_w);

    cvt_kernel<<<192, 256>>>((const float4*)qkv_w, (bf162*)(wb + WOFF_QKV), 49152);
    cvt_kernel<<<64,  256>>>((const float4*)pw,    (bf162*)(wb + WOFF_P),   16384);
    cvt_kernel<<<256, 256>>>((const float4*)f1w,   (bf162*)(wb + WOFF_F1),  65536);
    cvt_kernel<<<256, 256>>>((const float4*)f2w,   (bf162*)(wb + WOFF_F2),  65536);

    const int MBLK = NTOK / 128;   // 1344

    ln_roll_kernel<<<NTOK/8, 256>>>(x, n1g, n1b, h0b);
    bgemm_kernel<0,1><<<dim3(6, MBLK), 256>>>(h0b, wb + WOFF_QKV, qkv_b, nullptr, qkvb, NTOK, 768, 256);
    attn_kernel<<<dim3(NBWIN, NHEAD), 256>>>(qkvb, bt, attb);
    bgemm_kernel<0,0><<<dim3(2, MBLK), 256>>>(attb, wb + WOFF_P, pb, nullptr, prj, NTOK, 256, 256);
    resid_ln2_kernel<<<NTOK/8, 256>>>(x, prj, n2g, n2b, x1, mb);
    bgemm_kernel<1,1><<<dim3(8, MBLK), 256>>>(mb, wb + WOFF_F1, f1b, nullptr, f1b_buf, NTOK, 1024, 256);
    bgemm_kernel<2,0><<<dim3(2, MBLK), 256>>>(f1b_buf, wb + WOFF_F2, f2b, x1, out, NTOK, 256, 1024);
}

// round 7
// speedup vs baseline: 4.5690x; 1.8205x over previous
#include <cuda_runtime.h>
#include <cuda_bf16.h>
#include <math.h>
#include <stdint.h>

// ---------------- problem constants ----------------
#define BSZ   64
#define LSEQ  2688
#define CDIM  256
#define WWIN  42
#define SSH   21
#define NHEAD 8
#define HDIM  32
#define NWIN  64
#define MLPH  1024
#define NTOK  (BSZ*LSEQ)    // 172032
#define NBWIN (BSZ*NWIN)    // 4096

typedef __nv_bfloat16  bf16;
typedef __nv_bfloat162 bf162;

// ---------------- scratch ----------------
__device__ bf16  gb_h0 [(size_t)NTOK*CDIM];
__device__ bf16  gb_qkv[(size_t)NTOK*3*CDIM];
__device__ bf16  gb_att[(size_t)NTOK*CDIM];
__device__ float g_prj [(size_t)NTOK*CDIM];
__device__ float g_x1  [(size_t)NTOK*CDIM];
__device__ bf16  gb_m  [(size_t)NTOK*CDIM];
__device__ bf16  gb_f1 [(size_t)NTOK*MLPH];
#define WOFF_QKV 0
#define WOFF_P   196608
#define WOFF_F1  262144
#define WOFF_F2  524288
__device__ bf16  gb_w  [786432];

// ---------------- fp32 -> bf16 convert -------------
__global__ __launch_bounds__(256) void cvt_kernel(
    const float4* __restrict__ s, bf162* __restrict__ d, int n4)
{
    int i = blockIdx.x*256 + threadIdx.x;
    if (i < n4) {
        float4 v = s[i];
        d[2*i]   = bf162{__float2bfloat16(v.x), __float2bfloat16(v.y)};
        d[2*i+1] = bf162{__float2bfloat16(v.z), __float2bfloat16(v.w)};
    }
}

// ---------------- LayerNorm (+cyclic shift) -> bf16 ----------
__global__ __launch_bounds__(256) void ln_roll_kernel(
    const float* __restrict__ x, const float* __restrict__ g,
    const float* __restrict__ b, bf16* __restrict__ out)
{
    int token = blockIdx.x * 8 + (threadIdx.x >> 5);
    int lane  = threadIdx.x & 31;
    int bi = token / LSEQ, l = token % LSEQ;
    int src = bi * LSEQ + (l + SSH) % LSEQ;
    const float4* xr = (const float4*)(x + (size_t)src * CDIM);
    float4 v0 = xr[lane], v1 = xr[lane + 32];
    float s  = v0.x+v0.y+v0.z+v0.w + v1.x+v1.y+v1.z+v1.w;
    float ss = v0.x*v0.x+v0.y*v0.y+v0.z*v0.z+v0.w*v0.w
             + v1.x*v1.x+v1.y*v1.y+v1.z*v1.z+v1.w*v1.w;
    #pragma unroll
    for (int o = 16; o; o >>= 1) {
        s  += __shfl_xor_sync(0xffffffffu, s,  o);
        ss += __shfl_xor_sync(0xffffffffu, ss, o);
    }
    float mean = s * (1.0f/CDIM);
    float var  = ss * (1.0f/CDIM) - mean*mean;
    float inv  = rsqrtf(var + 1e-5f);
    float4 g0 = ((const float4*)g)[lane], g1 = ((const float4*)g)[lane+32];
    float4 b0 = ((const float4*)b)[lane], b1 = ((const float4*)b)[lane+32];
    bf162* orow = (bf162*)(out + (size_t)token * CDIM);
    orow[2*lane]      = bf162{__float2bfloat16((v0.x-mean)*inv*g0.x+b0.x),
                              __float2bfloat16((v0.y-mean)*inv*g0.y+b0.y)};
    orow[2*lane+1]    = bf162{__float2bfloat16((v0.z-mean)*inv*g0.z+b0.z),
                              __float2bfloat16((v0.w-mean)*inv*g0.w+b0.w)};
    orow[64+2*lane]   = bf162{__float2bfloat16((v1.x-mean)*inv*g1.x+b1.x),
                              __float2bfloat16((v1.y-mean)*inv*g1.y+b1.y)};
    orow[64+2*lane+1] = bf162{__float2bfloat16((v1.z-mean)*inv*g1.z+b1.z),
                              __float2bfloat16((v1.w-mean)*inv*g1.w+b1.w)};
}

// ------------- residual (reverse shift) + LN2 : x1 fp32, m bf16 -----
__global__ __launch_bounds__(256) void resid_ln2_kernel(
    const float* __restrict__ x,  const float* __restrict__ po,
    const float* __restrict__ g,  const float* __restrict__ b,
    float* __restrict__ x1, bf16* __restrict__ m)
{
    int token = blockIdx.x * 8 + (threadIdx.x >> 5);
    int lane  = threadIdx.x & 31;
    int bi = token / LSEQ, l = token % LSEQ;
    int src = bi * LSEQ + (l - SSH + LSEQ) % LSEQ;
    const float4* xr = (const float4*)(x  + (size_t)token * CDIM);
    const float4* pr = (const float4*)(po + (size_t)src   * CDIM);
    float4 a0 = xr[lane], a1 = xr[lane+32];
    float4 p0 = pr[lane], p1 = pr[lane+32];
    float4 v0, v1;
    v0.x=a0.x+p0.x; v0.y=a0.y+p0.y; v0.z=a0.z+p0.z; v0.w=a0.w+p0.w;
    v1.x=a1.x+p1.x; v1.y=a1.y+p1.y; v1.z=a1.z+p1.z; v1.w=a1.w+p1.w;
    float4* x1r = (float4*)(x1 + (size_t)token * CDIM);
    x1r[lane] = v0; x1r[lane+32] = v1;
    float s  = v0.x+v0.y+v0.z+v0.w + v1.x+v1.y+v1.z+v1.w;
    float ss = v0.x*v0.x+v0.y*v0.y+v0.z*v0.z+v0.w*v0.w
             + v1.x*v1.x+v1.y*v1.y+v1.z*v1.z+v1.w*v1.w;
    #pragma unroll
    for (int o = 16; o; o >>= 1) {
        s  += __shfl_xor_sync(0xffffffffu, s,  o);
        ss += __shfl_xor_sync(0xffffffffu, ss, o);
    }
    float mean = s * (1.0f/CDIM);
    float var  = ss * (1.0f/CDIM) - mean*mean;
    float inv  = rsqrtf(var + 1e-5f);
    float4 g0 = ((const float4*)g)[lane], g1 = ((const float4*)g)[lane+32];
    float4 b0 = ((const float4*)b)[lane], b1 = ((const float4*)b)[lane+32];
    bf162* mr = (bf162*)(m + (size_t)token * CDIM);
    mr[2*lane]      = bf162{__float2bfloat16((v0.x-mean)*inv*g0.x+b0.x),
                            __float2bfloat16((v0.y-mean)*inv*g0.y+b0.y)};
    mr[2*lane+1]    = bf162{__float2bfloat16((v0.z-mean)*inv*g0.z+b0.z),
                            __float2bfloat16((v0.w-mean)*inv*g0.w+b0.w)};
    mr[64+2*lane]   = bf162{__float2bfloat16((v1.x-mean)*inv*g1.x+b1.x),
                            __float2bfloat16((v1.y-mean)*inv*g1.y+b1.y)};
    mr[64+2*lane+1] = bf162{__float2bfloat16((v1.z-mean)*inv*g1.z+b1.z),
                            __float2bfloat16((v1.w-mean)*inv*g1.w+b1.w)};
}

// ---------------- mma helpers ---------------------
__device__ __forceinline__ float gelu_exact(float v) {
    return 0.5f * v * (1.0f + erff(v * 0.70710678118654752f));
}
__device__ __forceinline__ void cpasync16(uint32_t saddr, const void* g) {
    asm volatile("cp.async.cg.shared.global [%0], [%1], 16;\n" :: "r"(saddr), "l"(g));
}
__device__ __forceinline__ void ldsm_x4(uint32_t* r, uint32_t a) {
    asm volatile("ldmatrix.sync.aligned.m8n8.x4.shared.b16 {%0,%1,%2,%3}, [%4];"
        : "=r"(r[0]), "=r"(r[1]), "=r"(r[2]), "=r"(r[3]) : "r"(a));
}
__device__ __forceinline__ void ldsm_x4t(uint32_t* r, uint32_t a) {
    asm volatile("ldmatrix.sync.aligned.m8n8.x4.trans.shared.b16 {%0,%1,%2,%3}, [%4];"
        : "=r"(r[0]), "=r"(r[1]), "=r"(r[2]), "=r"(r[3]) : "r"(a));
}
__device__ __forceinline__ void mma_bf16(
    float& c0, float& c1, float& c2, float& c3,
    uint32_t a0, uint32_t a1, uint32_t a2, uint32_t a3,
    uint32_t b0, uint32_t b1)
{
    asm volatile(
        "mma.sync.aligned.m16n8k16.row.col.f32.bf16.bf16.f32 "
        "{%0,%1,%2,%3}, {%4,%5,%6,%7}, {%8,%9}, {%0,%1,%2,%3};\n"
        : "+f"(c0), "+f"(c1), "+f"(c2), "+f"(c3)
        : "r"(a0), "r"(a1), "r"(a2), "r"(a3), "r"(b0), "r"(b1));
}
__device__ __forceinline__ uint32_t packbf(float x, float y) {
    bf162 p = bf162{__float2bfloat16(x), __float2bfloat16(y)};
    return *(uint32_t*)&p;
}

// ---------------- bf16 tensor-core GEMM (R3, unchanged) --------------
#define BKK  32
#define LDAg 40
#define LDBg 136
#define ASZ  (128*LDAg*2)
#define BSZB (BKK*LDBg*2)

template<int EPI, int OUTBF>
__global__ __launch_bounds__(256) void bgemm_kernel(
    const bf16* __restrict__ A, const bf16* __restrict__ Bw,
    const float* __restrict__ bias, const float* __restrict__ res,
    void* __restrict__ Cv, int M, int N, int K)
{
    __shared__ __align__(16) bf16 As[3][128*LDAg];
    __shared__ __align__(16) bf16 Bs[3][BKK*LDBg];

    const int tid  = threadIdx.x;
    const int warp = tid >> 5, lane = tid & 31;
    const int wm  = (warp >> 2) * 64;
    const int wn  = (warp & 3) * 32;
    const int grp = lane & 3;
    const int qid = lane >> 2;

    const int arow = tid >> 1, acol = (tid & 1) * 16;
    const int brow = tid >> 3, bcol = (tid & 7) * 16;
    const bf16* Ag = A  + (size_t)(blockIdx.y*128 + arow) * K + acol;
    const bf16* Bg = Bw + (size_t)brow * N + blockIdx.x*128 + bcol;

    const uint32_t asBase = (uint32_t)__cvta_generic_to_shared(&As[0][0]);
    const uint32_t bsBase = (uint32_t)__cvta_generic_to_shared(&Bs[0][0]);
    const uint32_t asOff = (uint32_t)(arow*LDAg + acol) * 2;
    const uint32_t bsOff = (uint32_t)(brow*LDBg + bcol) * 2;

    float acc[4][4][4];
    #pragma unroll
    for (int i = 0; i < 4; i++)
        #pragma unroll
        for (int j = 0; j < 4; j++)
            #pragma unroll
            for (int t = 0; t < 4; t++) acc[i][j][t] = 0.0f;

    const int NIT = K / BKK;

    #pragma unroll
    for (int s = 0; s < 2; s++) {
        const int k0 = s * BKK;
        uint32_t aB = asBase + s*ASZ, bB = bsBase + s*BSZB;
        cpasync16(aB + asOff,      Ag + k0);
        cpasync16(aB + asOff + 16, Ag + k0 + 8);
        cpasync16(bB + bsOff,      Bg + (size_t)k0*N);
        cpasync16(bB + bsOff + 16, Bg + (size_t)k0*N + 8);
        asm volatile("cp.async.commit_group;\n");
    }

    int buf = 0;
    for (int it = 0; it < NIT; it++) {
        asm volatile("cp.async.wait_group 1;\n");
        __syncthreads();

        if (it + 2 < NIT) {
            const int k0 = (it + 2) * BKK;
            int nb = (buf + 2 >= 3) ? buf - 1 : buf + 2;
            uint32_t aB = asBase + nb*ASZ, bB = bsBase + nb*BSZB;
            cpasync16(aB + asOff,      Ag + k0);
            cpasync16(aB + asOff + 16, Ag + k0 + 8);
            cpasync16(bB + bsOff,      Bg + (size_t)k0*N);
            cpasync16(bB + bsOff + 16, Bg + (size_t)k0*N + 8);
        }
        asm volatile("cp.async.commit_group;\n");

        uint32_t asB = asBase + buf*ASZ;
        uint32_t bsB = bsBase + buf*BSZB;

        #pragma unroll
        for (int ks = 0; ks < 2; ks++) {
            const int kb = ks * 16;
            uint32_t af[4][4];
            #pragma unroll
            for (int mi = 0; mi < 4; mi++) {
                int row = wm + mi*16 + (lane & 15);
                uint32_t addr = asB + ((uint32_t)(row*LDAg + kb + (lane >> 4)*8)) * 2;
                ldsm_x4(af[mi], addr);
            }
            uint32_t bfr[2][4];
            #pragma unroll
            for (int gj = 0; gj < 2; gj++) {
                int krow = kb + (lane & 7) + ((lane >> 3) & 1) * 8;
                int col  = wn + gj*16 + (lane >> 4) * 8;
                uint32_t addr = bsB + ((uint32_t)(krow*LDBg + col)) * 2;
                ldsm_x4t(bfr[gj], addr);
            }
            #pragma unroll
            for (int mi = 0; mi < 4; mi++)
                #pragma unroll
                for (int nj = 0; nj < 4; nj++)
                    mma_bf16(acc[mi][nj][0], acc[mi][nj][1],
                             acc[mi][nj][2], acc[mi][nj][3],
                             af[mi][0], af[mi][1], af[mi][2], af[mi][3],
                             bfr[nj >> 1][(nj & 1)*2], bfr[nj >> 1][(nj & 1)*2 + 1]);
        }
        buf = (buf + 1 >= 3) ? 0 : buf + 1;
    }

    const int row0 = blockIdx.y*128 + wm;
    const int col0 = blockIdx.x*128 + wn;
    #pragma unroll
    for (int mi = 0; mi < 4; mi++) {
        #pragma unroll
        for (int nj = 0; nj < 4; nj++) {
            int c = col0 + nj*8 + grp*2;
            float bv0 = bias[c], bv1 = bias[c+1];
            #pragma unroll
            for (int half = 0; half < 2; half++) {
                int r = row0 + mi*16 + qid + half*8;
                float v0 = acc[mi][nj][half*2+0] + bv0;
                float v1 = acc[mi][nj][half*2+1] + bv1;
                size_t off = (size_t)r * N + c;
                if (EPI == 1) { v0 = gelu_exact(v0); v1 = gelu_exact(v1); }
                if (EPI == 2) { v0 += res[off]; v1 += res[off+1]; }
                if (OUTBF) {
                    bf162 o = {__float2bfloat16(v0), __float2bfloat16(v1)};
                    *(bf162*)((bf16*)Cv + off) = o;
                } else {
                    float2 o = {v0, v1};
                    *(float2*)((float*)Cv + off) = o;
                }
            }
        }
    }
}

// ============ tensor-core windowed attention ==================
// One block per window (8 warps = 8 heads). Q/K/V in padded smem.
// S = QK^T via mma, register softmax (clamped bias index), P@V via mma.
#define APAD 40
#define ATT_SMEM (3*8*48*APAD*2 + 8*84*4)

__global__ __launch_bounds__(256) void attn_mma_kernel(
    const bf16* __restrict__ qkv, const float* __restrict__ bias_table,
    bf16* __restrict__ out)
{
    extern __shared__ __align__(16) char smraw[];
    bf16* sq = (bf16*)smraw;
    bf16* sk = sq + 8*48*APAD;
    bf16* sv = sk + 8*48*APAD;
    float* sb = (float*)(sv + 8*48*APAD);

    const int w = blockIdx.x;
    const int tid = threadIdx.x, warp = tid >> 5, lane = tid & 31;

    // ---- stage window qkv into per-head padded tiles ----
    const uint4* src = (const uint4*)(qkv + (size_t)w * WWIN * 768);
    for (int c = tid; c < WWIN*96; c += 256) {
        int t = c / 96, r = c - t*96;
        int kind = r >> 5;            // 0=q 1=k 2=v
        int hh   = (r & 31) >> 2;
        int d8   = r & 3;
        uint4 val = src[c];
        bf16* dst = (kind == 0 ? sq : (kind == 1 ? sk : sv))
                  + (hh*48 + t)*APAD + d8*8;
        *(uint4*)dst = val;
    }
    // zero pad rows 42..47
    for (int c = tid; c < 8*6*4; c += 256) {
        int hh = c / 24, r6 = (c / 4) % 6, d8 = c & 3;
        uint4 z = {0,0,0,0};
        *(uint4*)(sq + (hh*48 + 42 + r6)*APAD + d8*8) = z;
        *(uint4*)(sk + (hh*48 + 42 + r6)*APAD + d8*8) = z;
        *(uint4*)(sv + (hh*48 + 42 + r6)*APAD + d8*8) = z;
    }
    // bias table: sb[h][d] = bt[d*8+h], d in [0,83)
    for (int c = tid; c < 83*8; c += 256) {
        int d = c >> 3, hh = c & 7;
        sb[hh*84 + d] = bias_table[d*8 + hh];
    }
    __syncthreads();

    const int h = warp;
    const uint32_t qb = (uint32_t)__cvta_generic_to_shared(sq + h*48*APAD);
    const uint32_t kb = (uint32_t)__cvta_generic_to_shared(sk + h*48*APAD);
    const uint32_t vb = (uint32_t)__cvta_generic_to_shared(sv + h*48*APAD);
    const float* bh = sb + h*84;
    const bool lastw = ((w & (NWIN-1)) == NWIN-1);

    // ---- S = Q @ K^T : 3 m-tiles x 6 n-tiles, k = 32 (2 steps) ----
    float s[3][6][4];
    #pragma unroll
    for (int i = 0; i < 3; i++)
        #pragma unroll
        for (int j = 0; j < 6; j++)
            #pragma unroll
            for (int t = 0; t < 4; t++) s[i][j][t] = 0.0f;

    #pragma unroll
    for (int kt = 0; kt < 2; kt++) {
        uint32_t af[3][4], bfr[3][4];
        #pragma unroll
        for (int mi = 0; mi < 3; mi++) {
            int row = mi*16 + (lane & 15);
            ldsm_x4(af[mi], qb + ((uint32_t)(row*APAD + kt*16 + (lane >> 4)*8))*2);
        }
        #pragma unroll
        for (int np = 0; np < 3; np++) {
            int row = np*16 + (lane >> 4)*8 + (lane & 7);
            int col = kt*16 + ((lane >> 3) & 1)*8;
            ldsm_x4(bfr[np], kb + ((uint32_t)(row*APAD + col))*2);
        }
        #pragma unroll
        for (int mi = 0; mi < 3; mi++)
            #pragma unroll
            for (int nj = 0; nj < 6; nj++)
                mma_bf16(s[mi][nj][0], s[mi][nj][1], s[mi][nj][2], s[mi][nj][3],
                         af[mi][0], af[mi][1], af[mi][2], af[mi][3],
                         bfr[nj >> 1][(nj & 1)*2], bfr[nj >> 1][(nj & 1)*2 + 1]);
    }

    // ---- scale + bias + mask, then row softmax in fragments ----
    const int rA0 = lane >> 2;
    const int colb = (lane & 3)*2;
    #pragma unroll
    for (int mi = 0; mi < 3; mi++) {
        int rA = mi*16 + rA0, rB = rA + 8;
        #pragma unroll
        for (int nj = 0; nj < 6; nj++) {
            int c0 = nj*8 + colb, c1 = c0 + 1;
            // clamped bias indices (valid (r,c<42) pairs always land in [0,82])
            int dA0 = min(max(c0 - rA + 41, 0), 82);
            int dA1 = min(max(c1 - rA + 41, 0), 82);
            int dB0 = min(max(c0 - rB + 41, 0), 82);
            int dB1 = min(max(c1 - rB + 41, 0), 82);
            float v0 = s[mi][nj][0]*0.17677669529663688f + bh[dA0];
            float v1 = s[mi][nj][1]*0.17677669529663688f + bh[dA1];
            if (lastw && ((rA < SSH) != (c0 < SSH))) v0 -= 100.0f;
            if (lastw && ((rA < SSH) != (c1 < SSH))) v1 -= 100.0f;
            if (c0 >= WWIN) v0 = -1e30f;
            if (c1 >= WWIN) v1 = -1e30f;
            float v2 = s[mi][nj][2]*0.17677669529663688f + bh[dB0];
            float v3 = s[mi][nj][3]*0.17677669529663688f + bh[dB1];
            if (lastw && ((rB < SSH) != (c0 < SSH))) v2 -= 100.0f;
            if (lastw && ((rB < SSH) != (c1 < SSH))) v3 -= 100.0f;
            if (c0 >= WWIN) v2 = -1e30f;
            if (c1 >= WWIN) v3 = -1e30f;
            s[mi][nj][0] = v0; s[mi][nj][1] = v1;
            s[mi][nj][2] = v2; s[mi][nj][3] = v3;
        }
        float mxA = -1e30f, mxB = -1e30f;
        #pragma unroll
        for (int nj = 0; nj < 6; nj++) {
            mxA = fmaxf(mxA, fmaxf(s[mi][nj][0], s[mi][nj][1]));
            mxB = fmaxf(mxB, fmaxf(s[mi][nj][2], s[mi][nj][3]));
        }
        mxA = fmaxf(mxA, __shfl_xor_sync(0xffffffffu, mxA, 1));
        mxA = fmaxf(mxA, __shfl_xor_sync(0xffffffffu, mxA, 2));
        mxB = fmaxf(mxB, __shfl_xor_sync(0xffffffffu, mxB, 1));
        mxB = fmaxf(mxB, __shfl_xor_sync(0xffffffffu, mxB, 2));
        float smA = 0.0f, smB = 0.0f;
        #pragma unroll
        for (int nj = 0; nj < 6; nj++) {
            float e0 = __expf(s[mi][nj][0] - mxA);
            float e1 = __expf(s[mi][nj][1] - mxA);
            float e2 = __expf(s[mi][nj][2] - mxB);
            float e3 = __expf(s[mi][nj][3] - mxB);
            s[mi][nj][0] = e0; s[mi][nj][1] = e1;
            s[mi][nj][2] = e2; s[mi][nj][3] = e3;
            smA += e0 + e1; smB += e2 + e3;
        }
        smA += __shfl_xor_sync(0xffffffffu, smA, 1);
        smA += __shfl_xor_sync(0xffffffffu, smA, 2);
        smB += __shfl_xor_sync(0xffffffffu, smB, 1);
        smB += __shfl_xor_sync(0xffffffffu, smB, 2);
        float rAi = 1.0f / smA, rBi = 1.0f / smB;
        #pragma unroll
        for (int nj = 0; nj < 6; nj++) {
            s[mi][nj][0] *= rAi; s[mi][nj][1] *= rAi;
            s[mi][nj][2] *= rBi; s[mi][nj][3] *= rBi;
        }
    }

    // ---- O = P @ V : 3 m-tiles x 4 n-tiles (32 dims), k = 48 keys ----
    float o[3][4][4];
    #pragma unroll
    for (int i = 0; i < 3; i++)
        #pragma unroll
        for (int j = 0; j < 4; j++)
            #pragma unroll
            for (int t = 0; t < 4; t++) o[i][j][t] = 0.0f;

    #pragma unroll
    for (int kt = 0; kt < 3; kt++) {
        uint32_t bfr[2][4];
        #pragma unroll
        for (int gj = 0; gj < 2; gj++) {
            int krow = kt*16 + (lane & 7) + ((lane >> 3) & 1)*8;
            int col  = gj*16 + (lane >> 4)*8;
            ldsm_x4t(bfr[gj], vb + ((uint32_t)(krow*APAD + col))*2);
        }
        #pragma unroll
        for (int mi = 0; mi < 3; mi++) {
            uint32_t a0 = packbf(s[mi][2*kt][0],   s[mi][2*kt][1]);
            uint32_t a1 = packbf(s[mi][2*kt][2],   s[mi][2*kt][3]);
            uint32_t a2 = packbf(s[mi][2*kt+1][0], s[mi][2*kt+1][1]);
            uint32_t a3 = packbf(s[mi][2*kt+1][2], s[mi][2*kt+1][3]);
            #pragma unroll
            for (int nj = 0; nj < 4; nj++)
                mma_bf16(o[mi][nj][0], o[mi][nj][1], o[mi][nj][2], o[mi][nj][3],
                         a0, a1, a2, a3,
                         bfr[nj >> 1][(nj & 1)*2], bfr[nj >> 1][(nj & 1)*2 + 1]);
        }
    }

    // ---- store (rows < 42) ----
    #pragma unroll
    for (int mi = 0; mi < 3; mi++) {
        int rA = mi*16 + rA0, rB = rA + 8;
        #pragma unroll
        for (int nj = 0; nj < 4; nj++) {
            int c = nj*8 + colb;
            if (rA < WWIN) {
                bf162 p = bf162{__float2bfloat16(o[mi][nj][0]), __float2bfloat16(o[mi][nj][1])};
                *(bf162*)(out + ((size_t)w*WWIN + rA)*CDIM + h*HDIM + c) = p;
            }
            if (rB < WWIN) {
                bf162 p = bf162{__float2bfloat16(o[mi][nj][2]), __float2bfloat16(o[mi][nj][3])};
                *(bf162*)(out + ((size_t)w*WWIN + rB)*CDIM + h*HDIM + c) = p;
            }
        }
    }
}

// ---------------- host-side launch --------------------------
extern "C" void kernel_launch(void* const* d_in, const int* in_sizes, int n_in,
                              void* d_out, int out_size)
{
    const float* x     = (const float*)d_in[0];
    const float* n1g   = (const float*)d_in[1];
    const float* n1b   = (const float*)d_in[2];
    const float* qkv_w = (const float*)d_in[3];
    const float* qkv_b = (const float*)d_in[4];
    const float* bt    = (const float*)d_in[5];
    const float* pw    = (const float*)d_in[6];
    const float* pb    = (const float*)d_in[7];
    const float* n2g   = (const float*)d_in[8];
    const float* n2b   = (const float*)d_in[9];
    const float* f1w   = (const float*)d_in[10];
    const float* f1b   = (const float*)d_in[11];
    const float* f2w   = (const float*)d_in[12];
    const float* f2b   = (const float*)d_in[13];
    float* out = (float*)d_out;

    bf16 *h0b, *qkvb, *attb, *mb, *f1buf, *wb;
    float *prj, *x1;
    cudaGetSymbolAddress((void**)&h0b,  gb_h0);
    cudaGetSymbolAddress((void**)&qkvb, gb_qkv);
    cudaGetSymbolAddress((void**)&attb, gb_att);
    cudaGetSymbolAddress((void**)&prj,  g_prj);
    cudaGetSymbolAddress((void**)&x1,   g_x1);
    cudaGetSymbolAddress((void**)&mb,   gb_m);
    cudaGetSymbolAddress((void**)&f1buf,gb_f1);
    cudaGetSymbolAddress((void**)&wb,   gb_w);

    cudaFuncSetAttribute(attn_mma_kernel,
                         cudaFuncAttributeMaxDynamicSharedMemorySize, ATT_SMEM);

    cvt_kernel<<<192, 256>>>((const float4*)qkv_w, (bf162*)(wb + WOFF_QKV), 49152);
    cvt_kernel<<<64,  256>>>((const float4*)pw,    (bf162*)(wb + WOFF_P),   16384);
    cvt_kernel<<<256, 256>>>((const float4*)f1w,   (bf162*)(wb + WOFF_F1),  65536);
    cvt_kernel<<<256, 256>>>((const float4*)f2w,   (bf162*)(wb + WOFF_F2),  65536);

    const int MBLK = NTOK / 128;   // 1344

    ln_roll_kernel<<<NTOK/8, 256>>>(x, n1g, n1b, h0b);
    bgemm_kernel<0,1><<<dim3(6, MBLK), 256>>>(h0b, wb + WOFF_QKV, qkv_b, nullptr, qkvb, NTOK, 768, 256);
    attn_mma_kernel<<<NBWIN, 256, ATT_SMEM>>>(qkvb, bt, attb);
    bgemm_kernel<0,0><<<dim3(2, MBLK), 256>>>(attb, wb + WOFF_P, pb, nullptr, prj, NTOK, 256, 256);
    resid_ln2_kernel<<<NTOK/8, 256>>>(x, prj, n2g, n2b, x1, mb);
    bgemm_kernel<1,1><<<dim3(8, MBLK), 256>>>(mb, wb + WOFF_F1, f1b, nullptr, f1buf, NTOK, 1024, 256);
    bgemm_kernel<2,0><<<dim3(2, MBLK), 256>>>(f1buf, wb + WOFF_F2, f2b, x1, out, NTOK, 256, 1024);
}